// round 1
// baseline (speedup 1.0000x reference)
#include <cuda_runtime.h>
#include <cuda_bf16.h>
#include <math.h>

// ---------------------------------------------------------------------------
// Problem constants
// ---------------------------------------------------------------------------
namespace {
constexpr int nB = 2, nS = 2048, nH = 2048, nNH = 16, nNKV = 4, nDH = 128;
constexpr int nE = 8, nMI = 1408;
constexpr int nT = nB * nS;          // 4096 tokens
constexpr int GR = nT * 2;           // 8192 gathered (token, expert) rows
constexpr int MAXTILE = 136;         // ceil(8192/64) + 8 experts worst-case padding
constexpr float RMS_EPS = 1e-6f;
constexpr float QK_SCALE = 0.088388347648318447f;  // 1/sqrt(128)
}

// ---------------------------------------------------------------------------
// Scratch (device globals; no runtime allocation allowed)
// ---------------------------------------------------------------------------
__device__ float g_xn    [(size_t)nT * nH];
__device__ float g_q     [(size_t)nT * nNH * nDH];
__device__ float g_k     [(size_t)nT * nNKV * nDH];
__device__ float g_v     [(size_t)nT * nNKV * nDH];
__device__ float g_scores[(size_t)nB * nNH * nS * nS];   // 536 MB
__device__ float g_attn  [(size_t)nT * nH];
__device__ float g_hidden[(size_t)nT * nH];
__device__ float g_x2    [(size_t)nT * nH];
__device__ int   g_topi  [nT * 2];
__device__ float g_topw  [nT * 2];
__device__ int   g_counts[nE];
__device__ int   g_fill  [nE];
__device__ int   g_coff  [nE + 1];
__device__ int   g_tileE [MAXTILE];
__device__ int   g_tileR0[MAXTILE];
__device__ int   g_toklist[GR];
__device__ int   g_slot  [nT * 2];
__device__ float g_gbuf  [(size_t)GR * nMI];
__device__ float g_ubuf  [(size_t)GR * nMI];
__device__ float g_part  [(size_t)GR * nH];

// ---------------------------------------------------------------------------
// Reductions
// ---------------------------------------------------------------------------
__device__ __forceinline__ float warpSum(float v) {
    #pragma unroll
    for (int o = 16; o; o >>= 1) v += __shfl_xor_sync(0xffffffffu, v, o);
    return v;
}
__device__ __forceinline__ float warpMax(float v) {
    #pragma unroll
    for (int o = 16; o; o >>= 1) v = fmaxf(v, __shfl_xor_sync(0xffffffffu, v, o));
    return v;
}

// ---------------------------------------------------------------------------
// RMSNorm (256 threads per row)
// ---------------------------------------------------------------------------
__device__ __forceinline__ void rmsnorm_row(const float* __restrict__ x,
                                            const float* __restrict__ w,
                                            float* __restrict__ out) {
    int row = blockIdx.x;
    const float* xr = x + (size_t)row * nH;
    float ss = 0.f;
    for (int i = threadIdx.x; i < nH; i += blockDim.x) { float v = xr[i]; ss += v * v; }
    __shared__ float sm[8];
    int lane = threadIdx.x & 31, wid = threadIdx.x >> 5;
    ss = warpSum(ss);
    if (lane == 0) sm[wid] = ss;
    __syncthreads();
    if (wid == 0) {
        float v = (lane < 8) ? sm[lane] : 0.f;
        v = warpSum(v);
        if (lane == 0) sm[0] = rsqrtf(v / (float)nH + RMS_EPS);
    }
    __syncthreads();
    float inv = sm[0];
    float* orow = out + (size_t)row * nH;
    for (int i = threadIdx.x; i < nH; i += blockDim.x) orow[i] = xr[i] * inv * w[i];
}

__global__ void rmsnorm1_kernel(const float* __restrict__ hs, const float* __restrict__ w) {
    rmsnorm_row(hs, w, g_xn);
}
__global__ void rmsnorm2_kernel(const float* __restrict__ w) {
    rmsnorm_row(g_hidden, w, g_x2);
}

// ---------------------------------------------------------------------------
// Generic fp32 tiled GEMM body: C[m][n] = alpha * sum_k A[m][k]*B[k][n] (+res)
// BM=BN=64, BK=16, 256 threads, 4x4 per thread.
// TRB:    B stored [N][K] (row n, ldb strides over n)
// GATHER: A row index goes through g_toklist
// Mend is an exclusive bound on the GLOBAL row index (rows >= Mend skipped).
// N must be a multiple of 64 (true for every call here). K multiple of 16.
// ---------------------------------------------------------------------------
template <bool TRB, bool GATHER>
__device__ __forceinline__ void gemm_body(
    const float* __restrict__ A, int lda,
    const float* __restrict__ B, int ldb,
    float* __restrict__ C, int ldc,
    int Mend, int K, int m0, int n0, float alpha,
    const float* __restrict__ res)
{
    __shared__ float As[16][64];
    __shared__ float Bs[16][68];
    __shared__ int   rt[64];
    const int tid = threadIdx.x;

    if (tid < 64) {
        int m = m0 + tid;
        int r = (m < Mend) ? m : -1;
        if (GATHER && r >= 0) r = g_toklist[r];
        rt[tid] = r;
    }
    __syncthreads();

    float acc[4][4] = {};
    const int ty = tid >> 4, tx = tid & 15;
    const int am = tid >> 2, ak = (tid & 3) << 2;

    for (int k0 = 0; k0 < K; k0 += 16) {
        // A tile: 64 rows x 16 k, float4 per thread
        {
            int r = rt[am];
            float4 av = make_float4(0.f, 0.f, 0.f, 0.f);
            if (r >= 0) av = *reinterpret_cast<const float4*>(A + (size_t)r * lda + k0 + ak);
            As[ak + 0][am] = av.x; As[ak + 1][am] = av.y;
            As[ak + 2][am] = av.z; As[ak + 3][am] = av.w;
        }
        // B tile
        if (!TRB) {
            int bk = tid >> 4;
            int bn = (tid & 15) << 2;
            float4 bv = *reinterpret_cast<const float4*>(B + (size_t)(k0 + bk) * ldb + n0 + bn);
            *reinterpret_cast<float4*>(&Bs[bk][bn]) = bv;
        } else {
            int bn = tid >> 2;
            int bk = (tid & 3) << 2;
            float4 bv = *reinterpret_cast<const float4*>(B + (size_t)(n0 + bn) * ldb + k0 + bk);
            Bs[bk + 0][bn] = bv.x; Bs[bk + 1][bn] = bv.y;
            Bs[bk + 2][bn] = bv.z; Bs[bk + 3][bn] = bv.w;
        }
        __syncthreads();

        #pragma unroll
        for (int kk = 0; kk < 16; kk++) {
            float4 a = *reinterpret_cast<const float4*>(&As[kk][ty << 2]);
            float4 b = *reinterpret_cast<const float4*>(&Bs[kk][tx << 2]);
            acc[0][0] += a.x * b.x; acc[0][1] += a.x * b.y; acc[0][2] += a.x * b.z; acc[0][3] += a.x * b.w;
            acc[1][0] += a.y * b.x; acc[1][1] += a.y * b.y; acc[1][2] += a.y * b.z; acc[1][3] += a.y * b.w;
            acc[2][0] += a.z * b.x; acc[2][1] += a.z * b.y; acc[2][2] += a.z * b.z; acc[2][3] += a.z * b.w;
            acc[3][0] += a.w * b.x; acc[3][1] += a.w * b.y; acc[3][2] += a.w * b.z; acc[3][3] += a.w * b.w;
        }
        __syncthreads();
    }

    #pragma unroll
    for (int i = 0; i < 4; i++) {
        int m = m0 + (ty << 2) + i;
        if (m >= Mend) continue;
        float* crow = C + (size_t)m * ldc + n0 + (tx << 2);
        const float* rrow = res ? (res + (size_t)m * ldc + n0 + (tx << 2)) : nullptr;
        #pragma unroll
        for (int j = 0; j < 4; j++) {
            float v = acc[i][j] * alpha;
            if (res) v += rrow[j];
            crow[j] = v;
        }
    }
}

// ---------------------------------------------------------------------------
// GEMM wrapper kernels
// ---------------------------------------------------------------------------
__global__ void __launch_bounds__(256) proj_q_kernel(const float* __restrict__ W) {
    gemm_body<false, false>(g_xn, nH, W, nNH * nDH, g_q, nNH * nDH,
                            nT, nH, blockIdx.y * 64, blockIdx.x * 64, 1.f, nullptr);
}
__global__ void __launch_bounds__(256) proj_k_kernel(const float* __restrict__ W) {
    gemm_body<false, false>(g_xn, nH, W, nNKV * nDH, g_k, nNKV * nDH,
                            nT, nH, blockIdx.y * 64, blockIdx.x * 64, 1.f, nullptr);
}
__global__ void __launch_bounds__(256) proj_v_kernel(const float* __restrict__ W) {
    gemm_body<false, false>(g_xn, nH, W, nNKV * nDH, g_v, nNKV * nDH,
                            nT, nH, blockIdx.y * 64, blockIdx.x * 64, 1.f, nullptr);
}
__global__ void __launch_bounds__(256) proj_o_kernel(const float* __restrict__ W,
                                                     const float* __restrict__ res) {
    gemm_body<false, false>(g_attn, nH, W, nH, g_hidden, nH,
                            nT, nH, blockIdx.y * 64, blockIdx.x * 64, 1.f, res);
}

__global__ void __launch_bounds__(256) qk_kernel() {
    int z = blockIdx.z, b = z / nNH, h = z % nNH, kh = h / (nNH / nNKV);
    const float* A  = g_q + (size_t)b * nS * (nNH * nDH) + h * nDH;
    const float* Bm = g_k + (size_t)b * nS * (nNKV * nDH) + kh * nDH;
    float* C = g_scores + (size_t)z * nS * nS;
    gemm_body<true, false>(A, nNH * nDH, Bm, nNKV * nDH, C, nS,
                           nS, nDH, blockIdx.y * 64, blockIdx.x * 64, QK_SCALE, nullptr);
}
__global__ void __launch_bounds__(256) av_kernel() {
    int z = blockIdx.z, b = z / nNH, h = z % nNH, kh = h / (nNH / nNKV);
    const float* A  = g_scores + (size_t)z * nS * nS;
    const float* Bm = g_v + (size_t)b * nS * (nNKV * nDH) + kh * nDH;
    float* C = g_attn + (size_t)b * nS * nH + h * nDH;
    gemm_body<false, false>(A, nS, Bm, nNKV * nDH, C, nH,
                            nS, nS, blockIdx.y * 64, blockIdx.x * 64, 1.f, nullptr);
}

// MoE GEMMs (per-expert tiles via device tile table)
__global__ void __launch_bounds__(256) moe_gateup_kernel(const float* __restrict__ W, int which) {
    int e = g_tileE[blockIdx.y];
    if (e < 0) return;
    float* out = which ? g_ubuf : g_gbuf;
    gemm_body<false, true>(g_x2, nH, W + (size_t)e * nH * nMI, nMI, out, nMI,
                           g_coff[e + 1], nH, g_tileR0[blockIdx.y], blockIdx.x * 64, 1.f, nullptr);
}
__global__ void __launch_bounds__(256) moe_down_kernel(const float* __restrict__ W) {
    int e = g_tileE[blockIdx.y];
    if (e < 0) return;
    gemm_body<false, false>(g_ubuf, nMI, W + (size_t)e * nMI * nH, nH, g_part, nH,
                            g_coff[e + 1], nMI, g_tileR0[blockIdx.y], blockIdx.x * 64, 1.f, nullptr);
}

// ---------------------------------------------------------------------------
// RoPE (in-place on q and k)
// ---------------------------------------------------------------------------
__global__ void rope_kernel(const float* __restrict__ cosb, const float* __restrict__ sinb) {
    int i = blockIdx.x * blockDim.x + threadIdx.x;
    if (i >= nT * (nNH + nNKV) * 64) return;
    int d  = i & 63;
    int hh = (i >> 6) % (nNH + nNKV);
    int t  = i / (64 * (nNH + nNKV));
    float* ptr = (hh < nNH)
        ? (g_q + (size_t)t * (nNH * nDH) + hh * nDH)
        : (g_k + (size_t)t * (nNKV * nDH) + (hh - nNH) * nDH);
    float x1 = ptr[d], x2 = ptr[d + 64];
    const float* cr = cosb + (size_t)t * nDH;
    const float* sr = sinb + (size_t)t * nDH;
    ptr[d]      = x1 * cr[d]      - x2 * sr[d];
    ptr[d + 64] = x2 * cr[d + 64] + x1 * sr[d + 64];
}

// ---------------------------------------------------------------------------
// Row softmax over scores (one block per row of 2048)
// ---------------------------------------------------------------------------
__global__ void softmax_kernel() {
    size_t row = blockIdx.x;
    float* p = g_scores + row * (size_t)nS;
    __shared__ float sm[8];
    int lane = threadIdx.x & 31, wid = threadIdx.x >> 5;

    float mx = -1e30f;
    for (int i = threadIdx.x; i < nS; i += 256) mx = fmaxf(mx, p[i]);
    mx = warpMax(mx);
    if (lane == 0) sm[wid] = mx;
    __syncthreads();
    if (wid == 0) {
        float v = (lane < 8) ? sm[lane] : -1e30f;
        v = warpMax(v);
        if (lane == 0) sm[0] = v;
    }
    __syncthreads();
    mx = sm[0];
    __syncthreads();

    float s = 0.f;
    for (int i = threadIdx.x; i < nS; i += 256) { float e = expf(p[i] - mx); p[i] = e; s += e; }
    s = warpSum(s);
    if (lane == 0) sm[wid] = s;
    __syncthreads();
    if (wid == 0) {
        float v = (lane < 8) ? sm[lane] : 0.f;
        v = warpSum(v);
        if (lane == 0) sm[0] = v;
    }
    __syncthreads();
    float inv = 1.f / sm[0];
    for (int i = threadIdx.x; i < nS; i += 256) p[i] *= inv;
}

// ---------------------------------------------------------------------------
// Router: per-token logits, softmax over 8, top-2, normalized weights
// ---------------------------------------------------------------------------
__global__ void router_kernel(const float* __restrict__ rw) {
    __shared__ float xs[nH];
    __shared__ float lg[nE];
    int t = blockIdx.x;
    for (int i = threadIdx.x; i < nH; i += blockDim.x) xs[i] = g_x2[(size_t)t * nH + i];
    __syncthreads();
    int w = threadIdx.x >> 5, lane = threadIdx.x & 31;
    float s = 0.f;
    for (int i = lane; i < nH; i += 32) s += xs[i] * rw[(size_t)i * nE + w];
    s = warpSum(s);
    if (lane == 0) lg[w] = s;
    __syncthreads();
    if (threadIdx.x == 0) {
        float mx = lg[0];
        #pragma unroll
        for (int e = 1; e < nE; e++) mx = fmaxf(mx, lg[e]);
        float p[nE]; float sum = 0.f;
        #pragma unroll
        for (int e = 0; e < nE; e++) { p[e] = expf(lg[e] - mx); sum += p[e]; }
        #pragma unroll
        for (int e = 0; e < nE; e++) p[e] /= sum;
        int i1 = 0;
        #pragma unroll
        for (int e = 1; e < nE; e++) if (p[e] > p[i1]) i1 = e;   // first-occurrence max
        int i2 = (i1 == 0) ? 1 : 0;
        #pragma unroll
        for (int e = 0; e < nE; e++) if (e != i1 && p[e] > p[i2]) i2 = e;
        float s2 = p[i1] + p[i2];
        g_topi[t * 2] = i1; g_topi[t * 2 + 1] = i2;
        g_topw[t * 2] = p[i1] / s2; g_topw[t * 2 + 1] = p[i2] / s2;
    }
}

// ---------------------------------------------------------------------------
// MoE bookkeeping
// ---------------------------------------------------------------------------
__global__ void reset_kernel() {
    int i = threadIdx.x;
    if (i < nE) { g_counts[i] = 0; g_fill[i] = 0; }
}
__global__ void count_kernel() {
    int t = blockIdx.x * blockDim.x + threadIdx.x;
    if (t >= nT) return;
    atomicAdd(&g_counts[g_topi[t * 2]], 1);
    atomicAdd(&g_counts[g_topi[t * 2 + 1]], 1);
}
__global__ void scan_kernel() {
    if (threadIdx.x != 0) return;
    int off = 0, nt = 0;
    for (int e = 0; e < nE; e++) {
        g_coff[e] = off;
        int ne = g_counts[e];
        int ntl = (ne + 63) >> 6;
        for (int i = 0; i < ntl; i++) { g_tileE[nt] = e; g_tileR0[nt] = off + i * 64; nt++; }
        off += ne;
    }
    g_coff[nE] = off;
    for (int i = nt; i < MAXTILE; i++) g_tileE[i] = -1;
}
__global__ void scatter_kernel() {
    int t = blockIdx.x * blockDim.x + threadIdx.x;
    if (t >= nT) return;
    #pragma unroll
    for (int k = 0; k < 2; k++) {
        int e = g_topi[t * 2 + k];
        int pos = g_coff[e] + atomicAdd(&g_fill[e], 1);
        g_toklist[pos] = t;
        g_slot[t * 2 + k] = pos;
    }
}

// silu(g) * u -> ubuf
__global__ void silu_kernel() {
    size_t i = (size_t)blockIdx.x * blockDim.x + threadIdx.x;
    if (i >= (size_t)GR * nMI) return;
    float gv = g_gbuf[i];
    g_ubuf[i] = gv * (1.f / (1.f + expf(-gv))) * g_ubuf[i];
}

// out = hidden + w0*part[slot0] + w1*part[slot1]
__global__ void combine_kernel(float* __restrict__ out) {
    size_t i = (size_t)blockIdx.x * blockDim.x + threadIdx.x;
    if (i >= (size_t)nT * nH) return;
    int t = (int)(i / nH), j = (int)(i % nH);
    float v = g_hidden[i];
    v += g_topw[t * 2]     * g_part[(size_t)g_slot[t * 2]     * nH + j];
    v += g_topw[t * 2 + 1] * g_part[(size_t)g_slot[t * 2 + 1] * nH + j];
    out[i] = v;
}

// ---------------------------------------------------------------------------
// Launch
// ---------------------------------------------------------------------------
extern "C" void kernel_launch(void* const* d_in, const int* in_sizes, int n_in,
                              void* d_out, int out_size) {
    const float* hs   = (const float*)d_in[0];
    const float* cosb = (const float*)d_in[1];
    const float* sinb = (const float*)d_in[2];
    const float* wq   = (const float*)d_in[3];
    const float* wk   = (const float*)d_in[4];
    const float* wv   = (const float*)d_in[5];
    const float* wo   = (const float*)d_in[6];
    const float* ln1  = (const float*)d_in[7];
    const float* ln2  = (const float*)d_in[8];
    const float* rw   = (const float*)d_in[9];
    const float* gw   = (const float*)d_in[10];
    const float* uw   = (const float*)d_in[11];
    const float* dw   = (const float*)d_in[12];
    float* out = (float*)d_out;

    reset_kernel<<<1, 32>>>();
    rmsnorm1_kernel<<<nT, 256>>>(hs, ln1);

    proj_q_kernel<<<dim3((nNH * nDH) / 64, nT / 64), 256>>>(wq);     // (32,64)
    proj_k_kernel<<<dim3((nNKV * nDH) / 64, nT / 64), 256>>>(wk);    // (8,64)
    proj_v_kernel<<<dim3((nNKV * nDH) / 64, nT / 64), 256>>>(wv);

    rope_kernel<<<(nT * (nNH + nNKV) * 64) / 256, 256>>>(cosb, sinb);

    qk_kernel<<<dim3(nS / 64, nS / 64, nB * nNH), 256>>>();          // (32,32,32)
    softmax_kernel<<<nB * nNH * nS, 256>>>();                        // 65536 rows
    av_kernel<<<dim3(nDH / 64, nS / 64, nB * nNH), 256>>>();         // (2,32,32)

    proj_o_kernel<<<dim3(nH / 64, nT / 64), 256>>>(wo, hs);          // + residual

    rmsnorm2_kernel<<<nT, 256>>>(ln2);
    router_kernel<<<nT, 256>>>(rw);

    count_kernel<<<nT / 256, 256>>>();
    scan_kernel<<<1, 1>>>();
    scatter_kernel<<<nT / 256, 256>>>();

    moe_gateup_kernel<<<dim3(nMI / 64, MAXTILE), 256>>>(gw, 0);      // (22,136)
    moe_gateup_kernel<<<dim3(nMI / 64, MAXTILE), 256>>>(uw, 1);
    silu_kernel<<<((size_t)GR * nMI) / 256, 256>>>();                // 45056
    moe_down_kernel<<<dim3(nH / 64, MAXTILE), 256>>>(dw);            // (32,136)

    combine_kernel<<<((size_t)nT * nH) / 256, 256>>>(out);
}

// round 3
// speedup vs baseline: 2.6125x; 2.6125x over previous
#include <cuda_runtime.h>
#include <cuda_bf16.h>
#include <math.h>
#include <stdint.h>

// ---------------------------------------------------------------------------
// Problem constants
// ---------------------------------------------------------------------------
namespace {
constexpr int nB = 2, nS = 2048, nH = 2048, nNH = 16, nNKV = 4, nDH = 128;
constexpr int nE = 8, nMI = 1408;
constexpr int nT = nB * nS;          // 4096 tokens
constexpr int GR = nT * 2;           // 8192 gathered (token, expert) rows
constexpr int MAXTILE = 72;          // ceil(8192/128) + 8 experts padding
constexpr float RMS_EPS = 1e-6f;
constexpr float QK_SCALE = 0.088388347648318447f;  // 1/sqrt(128)
constexpr int SMEM_FLOATS = 4 * 128 * 36;          // 2 bufs x (A+B) tiles
constexpr int SMEM_BYTES = SMEM_FLOATS * 4;        // 73728
}

// ---------------------------------------------------------------------------
// Scratch (device globals)
// ---------------------------------------------------------------------------
__device__ float g_xn    [(size_t)nT * nH];
__device__ float g_q     [(size_t)nT * nNH * nDH];
__device__ float g_k     [(size_t)nT * nNKV * nDH];
__device__ float g_v     [(size_t)nT * nNKV * nDH];
__device__ float g_vT    [(size_t)nB * nNKV * nDH * nS];
__device__ float g_scores[(size_t)nB * nNH * nS * nS];   // 536 MB
__device__ float g_attn  [(size_t)nT * nH];
__device__ float g_hidden[(size_t)nT * nH];
__device__ float g_x2    [(size_t)nT * nH];
__device__ int   g_topi  [nT * 2];
__device__ float g_topw  [nT * 2];
__device__ int   g_counts[nE];
__device__ int   g_fill  [nE];
__device__ int   g_coff  [nE + 1];
__device__ int   g_tileE [MAXTILE];
__device__ int   g_tileR0[MAXTILE];
__device__ int   g_toklist[GR];
__device__ int   g_slot  [nT * 2];
__device__ float g_gbuf  [(size_t)GR * nMI];
__device__ float g_ubuf  [(size_t)GR * nMI];
__device__ float g_part  [(size_t)GR * nH];
// transposed weights [N][K] K-major
__device__ float g_wqT [(size_t)(nNH * nDH) * nH];
__device__ float g_wkT [(size_t)(nNKV * nDH) * nH];
__device__ float g_wvT [(size_t)(nNKV * nDH) * nH];
__device__ float g_woT [(size_t)nH * nH];
__device__ float g_gwT [(size_t)nE * nMI * nH];
__device__ float g_uwT [(size_t)nE * nMI * nH];
__device__ float g_dwT [(size_t)nE * nH * nMI];

// ---------------------------------------------------------------------------
// Helpers
// ---------------------------------------------------------------------------
__device__ __forceinline__ uint32_t smem_to_u32(const void* p) {
    uint32_t a;
    asm("{ .reg .u64 t; cvta.to.shared.u64 t, %1; cvt.u32.u64 %0, t; }" : "=r"(a) : "l"(p));
    return a;
}
__device__ __forceinline__ uint32_t tf32r(float x) {
    uint32_t r;
    asm("cvt.rna.tf32.f32 %0, %1;" : "=r"(r) : "f"(x));
    return r;
}
__device__ __forceinline__ void mma_tf32(float* d, const uint32_t* a, const uint32_t* b) {
    asm volatile("mma.sync.aligned.m16n8k8.row.col.f32.tf32.tf32.f32 "
        "{%0,%1,%2,%3}, {%4,%5,%6,%7}, {%8,%9}, {%0,%1,%2,%3};"
        : "+f"(d[0]), "+f"(d[1]), "+f"(d[2]), "+f"(d[3])
        : "r"(a[0]), "r"(a[1]), "r"(a[2]), "r"(a[3]), "r"(b[0]), "r"(b[1]));
}
__device__ __forceinline__ float warpSum(float v) {
    #pragma unroll
    for (int o = 16; o; o >>= 1) v += __shfl_xor_sync(0xffffffffu, v, o);
    return v;
}
__device__ __forceinline__ float warpMax(float v) {
    #pragma unroll
    for (int o = 16; o; o >>= 1) v = fmaxf(v, __shfl_xor_sync(0xffffffffu, v, o));
    return v;
}

// ---------------------------------------------------------------------------
// tf32 mma.sync GEMM: C[M,N] = alpha * A[M,K](K-major) x B[N,K](K-major) (+res)
// CTA tile 128x128, K-chunks of 32, 256 threads (8 warps, 4m x 2n).
// ---------------------------------------------------------------------------
struct GArgs {
    const float* A; const float* B; float* C; const float* res;
    long long lda, ldb, ldc;
    int M, N, K;
    float alpha;
    int mode;   // 0 normal, 1 moe gather-A, 2 moe no-gather
    long long sAb, sAh, sBb, sBh, sCb, sCh;
    int zmod, groups;
};

__global__ void __launch_bounds__(256) tc_gemm(GArgs g) {
    extern __shared__ float dsmf[];
    const int tid = threadIdx.x, lane = tid & 31, wid = tid >> 5;
    const int wm = wid & 3, wn = wid >> 2;
    const int gq = lane >> 2, qq = lane & 3;

    int m0, Mb;
    const float* Ab = g.A;
    const float* Bb = g.B;
    float* Cb = g.C;
    const float* resb = g.res;
    if (g.mode >= 1) {
        int e = g_tileE[blockIdx.y];
        if (e < 0) return;
        m0 = g_tileR0[blockIdx.y];
        Mb = g_coff[e + 1];
        Bb += (size_t)e * g.N * g.K;
    } else {
        m0 = blockIdx.y * 128;
        Mb = g.M;
        int bz = blockIdx.z;
        int b = bz / g.zmod, h = bz % g.zmod;
        Ab += (size_t)b * g.sAb + (size_t)h * g.sAh;
        Bb += (size_t)b * g.sBb + (size_t)(h / g.groups) * g.sBh;
        Cb += (size_t)b * g.sCb + (size_t)h * g.sCh;
        if (resb) resb += (size_t)b * g.sCb + (size_t)h * g.sCh;
    }
    const int n0 = blockIdx.x * 128;

    __shared__ int rt[128];
    if (tid < 128) {
        int m = m0 + tid;
        int r = (m < Mb) ? m : -1;
        if (g.mode == 1 && r >= 0) r = g_toklist[r];
        rt[tid] = r;
    }
    __syncthreads();

    const uint32_t sbase = smem_to_u32(dsmf);
    const int NC = g.K >> 5;

    auto issue = [&](int c, int s) {
        const int k0 = c << 5;
        #pragma unroll
        for (int p = 0; p < 4; p++) {
            int idx = p * 256 + tid;
            int row = idx >> 3, c4 = idx & 7;
            int r = rt[row];
            const float* src = (r >= 0 ? Ab + (size_t)r * g.lda : Ab) + k0 + c4 * 4;
            uint32_t dst = sbase + (uint32_t)(s * 4608 + row * 36 + c4 * 4) * 4u;
            int sz = (r >= 0) ? 16 : 0;
            asm volatile("cp.async.cg.shared.global [%0], [%1], 16, %2;"
                         :: "r"(dst), "l"(src), "r"(sz) : "memory");
        }
        #pragma unroll
        for (int p = 0; p < 4; p++) {
            int idx = p * 256 + tid;
            int row = idx >> 3, c4 = idx & 7;
            const float* src = Bb + (size_t)(n0 + row) * g.ldb + k0 + c4 * 4;
            uint32_t dst = sbase + (uint32_t)(9216 + s * 4608 + row * 36 + c4 * 4) * 4u;
            asm volatile("cp.async.cg.shared.global [%0], [%1], 16, %2;"
                         :: "r"(dst), "l"(src), "r"(16) : "memory");
        }
    };

    float acc[2][8][4] = {};

    issue(0, 0);
    asm volatile("cp.async.commit_group;" ::: "memory");
    if (NC > 1) issue(1, 1);
    asm volatile("cp.async.commit_group;" ::: "memory");

    for (int c = 0; c < NC; c++) {
        const int s = c & 1;
        asm volatile("cp.async.wait_group 1;" ::: "memory");
        __syncthreads();
        const float* Asm = dsmf + s * 4608;
        const float* Bsm = dsmf + 9216 + s * 4608;
        #pragma unroll
        for (int kk = 0; kk < 4; kk++) {
            const int kb = kk * 8;
            uint32_t af[2][4];
            #pragma unroll
            for (int mt = 0; mt < 2; mt++) {
                int r0 = wm * 32 + mt * 16 + gq;
                af[mt][0] = tf32r(Asm[r0 * 36 + kb + qq]);
                af[mt][1] = tf32r(Asm[(r0 + 8) * 36 + kb + qq]);
                af[mt][2] = tf32r(Asm[r0 * 36 + kb + qq + 4]);
                af[mt][3] = tf32r(Asm[(r0 + 8) * 36 + kb + qq + 4]);
            }
            uint32_t bf[8][2];
            #pragma unroll
            for (int nt = 0; nt < 8; nt++) {
                int c0 = wn * 64 + nt * 8 + gq;
                bf[nt][0] = tf32r(Bsm[c0 * 36 + kb + qq]);
                bf[nt][1] = tf32r(Bsm[c0 * 36 + kb + qq + 4]);
            }
            #pragma unroll
            for (int mt = 0; mt < 2; mt++)
                #pragma unroll
                for (int nt = 0; nt < 8; nt++)
                    mma_tf32(acc[mt][nt], af[mt], bf[nt]);
        }
        __syncthreads();
        if (c + 2 < NC) issue(c + 2, s);
        asm volatile("cp.async.commit_group;" ::: "memory");
    }

    // Epilogue
    #pragma unroll
    for (int mt = 0; mt < 2; mt++) {
        int row = m0 + wm * 32 + mt * 16 + gq;
        #pragma unroll
        for (int half = 0; half < 2; half++) {
            int r = row + half * 8;
            if (r >= Mb) continue;
            float* crow = Cb + (size_t)r * g.ldc + n0 + wn * 64 + 2 * qq;
            const float* rrow = resb ? resb + (size_t)r * g.ldc + n0 + wn * 64 + 2 * qq : nullptr;
            #pragma unroll
            for (int nt = 0; nt < 8; nt++) {
                float2 v;
                v.x = acc[mt][nt][half * 2 + 0] * g.alpha;
                v.y = acc[mt][nt][half * 2 + 1] * g.alpha;
                if (rrow) {
                    float2 rv = *reinterpret_cast<const float2*>(rrow + nt * 8);
                    v.x += rv.x; v.y += rv.y;
                }
                *reinterpret_cast<float2*>(crow + nt * 8) = v;
            }
        }
    }
}

// ---------------------------------------------------------------------------
// Batched tiled transpose: in [z][K][N] -> out [z][N][K]
// ---------------------------------------------------------------------------
__global__ void transpose_kernel(const float* __restrict__ in, float* __restrict__ out,
                                 int K, int N) {
    __shared__ float t[32][33];
    size_t zo = (size_t)blockIdx.z * K * N;
    const float* ip = in + zo;
    float* op = out + zo;
    int n0 = blockIdx.x * 32, k0 = blockIdx.y * 32;
    int tx = threadIdx.x & 31, ty = threadIdx.x >> 5;
    #pragma unroll
    for (int i = ty; i < 32; i += 8) t[i][tx] = ip[(size_t)(k0 + i) * N + n0 + tx];
    __syncthreads();
    #pragma unroll
    for (int i = ty; i < 32; i += 8) op[(size_t)(n0 + i) * K + k0 + tx] = t[tx][i];
}

// V transpose: g_v [b*S][512] head kh cols -> g_vT [(b*4+kh)*128 + d][S]
__global__ void vtrans_kernel() {
    __shared__ float t[32][33];
    int z = blockIdx.z, b = z >> 2, kh = z & 3;
    int s0 = blockIdx.x * 32, d0 = blockIdx.y * 32;
    int tx = threadIdx.x & 31, ty = threadIdx.x >> 5;
    #pragma unroll
    for (int i = ty; i < 32; i += 8)
        t[i][tx] = g_v[((size_t)b * nS + s0 + i) * (nNKV * nDH) + kh * nDH + d0 + tx];
    __syncthreads();
    #pragma unroll
    for (int i = ty; i < 32; i += 8)
        g_vT[((size_t)z * nDH + d0 + i) * nS + s0 + tx] = t[tx][i];
}

// ---------------------------------------------------------------------------
// RMSNorm
// ---------------------------------------------------------------------------
__device__ __forceinline__ void rmsnorm_row(const float* __restrict__ x,
                                            const float* __restrict__ w,
                                            float* __restrict__ out) {
    int row = blockIdx.x;
    const float* xr = x + (size_t)row * nH;
    float ss = 0.f;
    for (int i = threadIdx.x; i < nH; i += blockDim.x) { float v = xr[i]; ss += v * v; }
    __shared__ float sm[8];
    int lane = threadIdx.x & 31, wid = threadIdx.x >> 5;
    ss = warpSum(ss);
    if (lane == 0) sm[wid] = ss;
    __syncthreads();
    if (wid == 0) {
        float v = (lane < 8) ? sm[lane] : 0.f;
        v = warpSum(v);
        if (lane == 0) sm[0] = rsqrtf(v / (float)nH + RMS_EPS);
    }
    __syncthreads();
    float inv = sm[0];
    float* orow = out + (size_t)row * nH;
    for (int i = threadIdx.x; i < nH; i += blockDim.x) orow[i] = xr[i] * inv * w[i];
}
__global__ void rmsnorm1_kernel(const float* __restrict__ hs, const float* __restrict__ w) {
    rmsnorm_row(hs, w, g_xn);
}
__global__ void rmsnorm2_kernel(const float* __restrict__ w) {
    rmsnorm_row(g_hidden, w, g_x2);
}

// ---------------------------------------------------------------------------
// RoPE (in-place on q and k)
// ---------------------------------------------------------------------------
__global__ void rope_kernel(const float* __restrict__ cosb, const float* __restrict__ sinb) {
    int i = blockIdx.x * blockDim.x + threadIdx.x;
    if (i >= nT * (nNH + nNKV) * 64) return;
    int d  = i & 63;
    int hh = (i >> 6) % (nNH + nNKV);
    int t  = i / (64 * (nNH + nNKV));
    float* ptr = (hh < nNH)
        ? (g_q + (size_t)t * (nNH * nDH) + hh * nDH)
        : (g_k + (size_t)t * (nNKV * nDH) + (hh - nNH) * nDH);
    float x1 = ptr[d], x2 = ptr[d + 64];
    const float* cr = cosb + (size_t)t * nDH;
    const float* sr = sinb + (size_t)t * nDH;
    ptr[d]      = x1 * cr[d]      - x2 * sr[d];
    ptr[d + 64] = x2 * cr[d + 64] + x1 * sr[d + 64];
}

// ---------------------------------------------------------------------------
// Row softmax over scores
// ---------------------------------------------------------------------------
__global__ void softmax_kernel() {
    size_t row = blockIdx.x;
    float* p = g_scores + row * (size_t)nS;
    __shared__ float sm[8];
    int lane = threadIdx.x & 31, wid = threadIdx.x >> 5;

    float mx = -1e30f;
    for (int i = threadIdx.x; i < nS; i += 256) mx = fmaxf(mx, p[i]);
    mx = warpMax(mx);
    if (lane == 0) sm[wid] = mx;
    __syncthreads();
    if (wid == 0) {
        float v = (lane < 8) ? sm[lane] : -1e30f;
        v = warpMax(v);
        if (lane == 0) sm[0] = v;
    }
    __syncthreads();
    mx = sm[0];
    __syncthreads();

    float s = 0.f;
    for (int i = threadIdx.x; i < nS; i += 256) { float e = expf(p[i] - mx); p[i] = e; s += e; }
    s = warpSum(s);
    if (lane == 0) sm[wid] = s;
    __syncthreads();
    if (wid == 0) {
        float v = (lane < 8) ? sm[lane] : 0.f;
        v = warpSum(v);
        if (lane == 0) sm[0] = v;
    }
    __syncthreads();
    float inv = 1.f / sm[0];
    for (int i = threadIdx.x; i < nS; i += 256) p[i] *= inv;
}

// ---------------------------------------------------------------------------
// Router
// ---------------------------------------------------------------------------
__global__ void router_kernel(const float* __restrict__ rw) {
    __shared__ float xs[nH];
    __shared__ float lg[nE];
    int t = blockIdx.x;
    for (int i = threadIdx.x; i < nH; i += blockDim.x) xs[i] = g_x2[(size_t)t * nH + i];
    __syncthreads();
    int w = threadIdx.x >> 5, lane = threadIdx.x & 31;
    float s = 0.f;
    for (int i = lane; i < nH; i += 32) s += xs[i] * rw[(size_t)i * nE + w];
    s = warpSum(s);
    if (lane == 0) lg[w] = s;
    __syncthreads();
    if (threadIdx.x == 0) {
        float mx = lg[0];
        #pragma unroll
        for (int e = 1; e < nE; e++) mx = fmaxf(mx, lg[e]);
        float p[nE]; float sum = 0.f;
        #pragma unroll
        for (int e = 0; e < nE; e++) { p[e] = expf(lg[e] - mx); sum += p[e]; }
        #pragma unroll
        for (int e = 0; e < nE; e++) p[e] /= sum;
        int i1 = 0;
        #pragma unroll
        for (int e = 1; e < nE; e++) if (p[e] > p[i1]) i1 = e;
        int i2 = (i1 == 0) ? 1 : 0;
        #pragma unroll
        for (int e = 0; e < nE; e++) if (e != i1 && p[e] > p[i2]) i2 = e;
        float s2 = p[i1] + p[i2];
        g_topi[t * 2] = i1; g_topi[t * 2 + 1] = i2;
        g_topw[t * 2] = p[i1] / s2; g_topw[t * 2 + 1] = p[i2] / s2;
    }
}

// ---------------------------------------------------------------------------
// MoE bookkeeping
// ---------------------------------------------------------------------------
__global__ void reset_kernel() {
    int i = threadIdx.x;
    if (i < nE) { g_counts[i] = 0; g_fill[i] = 0; }
}
__global__ void count_kernel() {
    int t = blockIdx.x * blockDim.x + threadIdx.x;
    if (t >= nT) return;
    atomicAdd(&g_counts[g_topi[t * 2]], 1);
    atomicAdd(&g_counts[g_topi[t * 2 + 1]], 1);
}
__global__ void scan_kernel() {
    if (threadIdx.x != 0) return;
    int off = 0, nt = 0;
    for (int e = 0; e < nE; e++) {
        g_coff[e] = off;
        int ne = g_counts[e];
        int ntl = (ne + 127) >> 7;
        for (int i = 0; i < ntl; i++) { g_tileE[nt] = e; g_tileR0[nt] = off + i * 128; nt++; }
        off += ne;
    }
    g_coff[nE] = off;
    for (int i = nt; i < MAXTILE; i++) g_tileE[i] = -1;
}
__global__ void scatter_kernel() {
    int t = blockIdx.x * blockDim.x + threadIdx.x;
    if (t >= nT) return;
    #pragma unroll
    for (int k = 0; k < 2; k++) {
        int e = g_topi[t * 2 + k];
        int pos = g_coff[e] + atomicAdd(&g_fill[e], 1);
        g_toklist[pos] = t;
        g_slot[t * 2 + k] = pos;
    }
}

__global__ void silu_kernel() {
    size_t i = (size_t)blockIdx.x * blockDim.x + threadIdx.x;
    if (i >= (size_t)GR * nMI) return;
    float gv = g_gbuf[i];
    g_ubuf[i] = gv * (1.f / (1.f + expf(-gv))) * g_ubuf[i];
}

__global__ void combine_kernel(float* __restrict__ out) {
    size_t i = (size_t)blockIdx.x * blockDim.x + threadIdx.x;
    if (i >= (size_t)nT * nH) return;
    int t = (int)(i / nH), j = (int)(i % nH);
    float v = g_hidden[i];
    v += g_topw[t * 2]     * g_part[(size_t)g_slot[t * 2]     * nH + j];
    v += g_topw[t * 2 + 1] * g_part[(size_t)g_slot[t * 2 + 1] * nH + j];
    out[i] = v;
}

// ---------------------------------------------------------------------------
// Launch
// ---------------------------------------------------------------------------
static void launch_gemm(const float* A, long long lda, const float* B, long long ldb,
                        float* C, long long ldc, const float* res,
                        int M, int N, int K, float alpha, int mode,
                        dim3 grid,
                        long long sAb = 0, long long sAh = 0, long long sBb = 0,
                        long long sBh = 0, long long sCb = 0, long long sCh = 0,
                        int zmod = 1, int groups = 1) {
    GArgs g;
    g.A = A; g.B = B; g.C = C; g.res = res;
    g.lda = lda; g.ldb = ldb; g.ldc = ldc;
    g.M = M; g.N = N; g.K = K; g.alpha = alpha; g.mode = mode;
    g.sAb = sAb; g.sAh = sAh; g.sBb = sBb; g.sBh = sBh; g.sCb = sCb; g.sCh = sCh;
    g.zmod = zmod; g.groups = groups;
    tc_gemm<<<grid, 256, SMEM_BYTES>>>(g);
}

extern "C" void kernel_launch(void* const* d_in, const int* in_sizes, int n_in,
                              void* d_out, int out_size) {
    const float* hs   = (const float*)d_in[0];
    const float* cosb = (const float*)d_in[1];
    const float* sinb = (const float*)d_in[2];
    const float* wq   = (const float*)d_in[3];
    const float* wk   = (const float*)d_in[4];
    const float* wv   = (const float*)d_in[5];
    const float* wo   = (const float*)d_in[6];
    const float* ln1  = (const float*)d_in[7];
    const float* ln2  = (const float*)d_in[8];
    const float* rw   = (const float*)d_in[9];
    const float* gw   = (const float*)d_in[10];
    const float* uw   = (const float*)d_in[11];
    const float* dw   = (const float*)d_in[12];
    float* out = (float*)d_out;

    static bool attr_set = false;
    if (!attr_set) {
        cudaFuncSetAttribute(tc_gemm, cudaFuncAttributeMaxDynamicSharedMemorySize, SMEM_BYTES);
        attr_set = true;
    }

    float* wqT; cudaGetSymbolAddress((void**)&wqT, g_wqT);
    float* wkT; cudaGetSymbolAddress((void**)&wkT, g_wkT);
    float* wvT; cudaGetSymbolAddress((void**)&wvT, g_wvT);
    float* woT; cudaGetSymbolAddress((void**)&woT, g_woT);
    float* gwT; cudaGetSymbolAddress((void**)&gwT, g_gwT);
    float* uwT; cudaGetSymbolAddress((void**)&uwT, g_uwT);
    float* dwT; cudaGetSymbolAddress((void**)&dwT, g_dwT);
    float* xn;  cudaGetSymbolAddress((void**)&xn, g_xn);
    float* q;   cudaGetSymbolAddress((void**)&q, g_q);
    float* k;   cudaGetSymbolAddress((void**)&k, g_k);
    float* v;   cudaGetSymbolAddress((void**)&v, g_v);
    float* vT;  cudaGetSymbolAddress((void**)&vT, g_vT);
    float* sc;  cudaGetSymbolAddress((void**)&sc, g_scores);
    float* at;  cudaGetSymbolAddress((void**)&at, g_attn);
    float* hid; cudaGetSymbolAddress((void**)&hid, g_hidden);
    float* x2;  cudaGetSymbolAddress((void**)&x2, g_x2);
    float* gb;  cudaGetSymbolAddress((void**)&gb, g_gbuf);
    float* ub;  cudaGetSymbolAddress((void**)&ub, g_ubuf);
    float* pt;  cudaGetSymbolAddress((void**)&pt, g_part);

    reset_kernel<<<1, 32>>>();

    // Weight transposes -> [N][K]
    transpose_kernel<<<dim3(64, 64, 1), 256>>>(wq, wqT, nH, nNH * nDH);
    transpose_kernel<<<dim3(16, 64, 1), 256>>>(wk, wkT, nH, nNKV * nDH);
    transpose_kernel<<<dim3(16, 64, 1), 256>>>(wv, wvT, nH, nNKV * nDH);
    transpose_kernel<<<dim3(64, 64, 1), 256>>>(wo, woT, nH, nH);
    transpose_kernel<<<dim3(44, 64, nE), 256>>>(gw, gwT, nH, nMI);
    transpose_kernel<<<dim3(44, 64, nE), 256>>>(uw, uwT, nH, nMI);
    transpose_kernel<<<dim3(64, 44, nE), 256>>>(dw, dwT, nMI, nH);

    rmsnorm1_kernel<<<nT, 256>>>(hs, ln1);

    launch_gemm(xn, nH, wqT, nH, q, nNH * nDH, nullptr, nT, nNH * nDH, nH, 1.f, 0,
                dim3(16, 32, 1));
    launch_gemm(xn, nH, wkT, nH, k, nNKV * nDH, nullptr, nT, nNKV * nDH, nH, 1.f, 0,
                dim3(4, 32, 1));
    launch_gemm(xn, nH, wvT, nH, v, nNKV * nDH, nullptr, nT, nNKV * nDH, nH, 1.f, 0,
                dim3(4, 32, 1));

    rope_kernel<<<(nT * (nNH + nNKV) * 64) / 256, 256>>>(cosb, sinb);
    vtrans_kernel<<<dim3(nS / 32, nDH / 32, nB * nNKV), 256>>>();

    // scores = Q K^T * scale    (B: k rows [N=token, K=dh], already K-major)
    launch_gemm(q, nNH * nDH, k, nNKV * nDH, sc, nS, nullptr, nS, nS, nDH, QK_SCALE, 0,
                dim3(16, 16, nB * nNH),
                (long long)nS * nNH * nDH, nDH,
                (long long)nS * nNKV * nDH, nDH,
                (long long)nNH * nS * nS, (long long)nS * nS,
                nNH, nNH / nNKV);

    softmax_kernel<<<nB * nNH * nS, 256>>>();

    // attn_out = P @ V          (B = V^T [dh][token])
    launch_gemm(sc, nS, vT, nS, at, nH, nullptr, nS, nDH, nS, 1.f, 0,
                dim3(1, 16, nB * nNH),
                (long long)nNH * nS * nS, (long long)nS * nS,
                (long long)nNKV * nDH * nS, (long long)nDH * nS,
                (long long)nS * nH, nDH,
                nNH, nNH / nNKV);

    // hidden = attn @ wo + residual
    launch_gemm(at, nH, woT, nH, hid, nH, hs, nT, nH, nH, 1.f, 0, dim3(16, 32, 1));

    rmsnorm2_kernel<<<nT, 256>>>(ln2);
    router_kernel<<<nT, 256>>>(rw);

    count_kernel<<<nT / 256, 256>>>();
    scan_kernel<<<1, 1>>>();
    scatter_kernel<<<nT / 256, 256>>>();

    // MoE: gate & up (gathered A), silu, down
    launch_gemm(x2, nH, gwT, nH, gb, nMI, nullptr, GR, nMI, nH, 1.f, 1, dim3(11, MAXTILE, 1));
    launch_gemm(x2, nH, uwT, nH, ub, nMI, nullptr, GR, nMI, nH, 1.f, 1, dim3(11, MAXTILE, 1));
    silu_kernel<<<((size_t)GR * nMI) / 256, 256>>>();
    launch_gemm(ub, nMI, dwT, nMI, pt, nH, nullptr, GR, nH, nMI, 1.f, 2, dim3(16, MAXTILE, 1));

    combine_kernel<<<((size_t)nT * nH) / 256, 256>>>(out);
}

// round 5
// speedup vs baseline: 3.2407x; 1.2405x over previous
#include <cuda_runtime.h>
#include <cuda_bf16.h>
#include <math.h>
#include <stdint.h>

// ---------------------------------------------------------------------------
// Problem constants
// ---------------------------------------------------------------------------
namespace {
constexpr int nB = 2, nS = 2048, nH = 2048, nNH = 16, nNKV = 4, nDH = 128;
constexpr int nE = 8, nMI = 1408;
constexpr int nT = nB * nS;          // 4096 tokens
constexpr int GR = nT * 2;           // 8192 gathered (token, expert) rows
constexpr int MAXTILE = 72;          // ceil(8192/128) + 8 experts padding
constexpr float RMS_EPS = 1e-6f;
constexpr float QK_SCALE = 0.088388347648318447f;  // 1/sqrt(128)
constexpr int SMEM_FLOATS = 4 * 128 * 36;          // 2 bufs x (A+B) tiles
constexpr int SMEM_BYTES = SMEM_FLOATS * 4;        // 73728
}

// ---------------------------------------------------------------------------
// Scratch (device globals)
// ---------------------------------------------------------------------------
__device__ float g_xn    [(size_t)nT * nH];   // rmsnorm1 out; later: unrounded rmsnorm2 out
__device__ float g_q     [(size_t)nT * nNH * nDH];
__device__ float g_k     [(size_t)nT * nNKV * nDH];
__device__ float g_v     [(size_t)nT * nNKV * nDH];
__device__ float g_vT    [(size_t)nB * nNKV * nDH * nS];
__device__ float g_scores[(size_t)nB * nNH * nS * nS];   // 536 MB
__device__ float g_attn  [(size_t)nT * nH];
__device__ float g_hidden[(size_t)nT * nH];
__device__ float g_x2    [(size_t)nT * nH];
__device__ int   g_topi  [nT * 2];
__device__ float g_topw  [nT * 2];
__device__ int   g_counts[nE];
__device__ int   g_fill  [nE];
__device__ int   g_coff  [nE + 1];
__device__ int   g_tileE [MAXTILE];
__device__ int   g_tileR0[MAXTILE];
__device__ int   g_toklist[GR];
__device__ int   g_slot  [nT * 2];
__device__ float g_gbuf  [(size_t)GR * nMI];
__device__ float g_ubuf  [(size_t)GR * nMI];
__device__ float g_part  [(size_t)GR * nH];
// transposed weights [N][K] K-major (tf32-rounded)
__device__ float g_wqT [(size_t)(nNH * nDH) * nH];
__device__ float g_wkT [(size_t)(nNKV * nDH) * nH];
__device__ float g_wvT [(size_t)(nNKV * nDH) * nH];
__device__ float g_woT [(size_t)nH * nH];
__device__ float g_gwT [(size_t)nE * nMI * nH];
__device__ float g_uwT [(size_t)nE * nMI * nH];
__device__ float g_dwT [(size_t)nE * nH * nMI];

// ---------------------------------------------------------------------------
// Helpers
// ---------------------------------------------------------------------------
__device__ __forceinline__ uint32_t smem_to_u32(const void* p) {
    uint32_t a;
    asm("{ .reg .u64 t; cvta.to.shared.u64 t, %1; cvt.u32.u64 %0, t; }" : "=r"(a) : "l"(p));
    return a;
}
__device__ __forceinline__ float rntf(float x) {
    uint32_t r;
    asm("cvt.rna.tf32.f32 %0, %1;" : "=r"(r) : "f"(x));
    return __uint_as_float(r);
}
__device__ __forceinline__ void mma_tf32(float* d, const uint32_t* a, const uint32_t* b) {
    asm volatile("mma.sync.aligned.m16n8k8.row.col.f32.tf32.tf32.f32 "
        "{%0,%1,%2,%3}, {%4,%5,%6,%7}, {%8,%9}, {%0,%1,%2,%3};"
        : "+f"(d[0]), "+f"(d[1]), "+f"(d[2]), "+f"(d[3])
        : "r"(a[0]), "r"(a[1]), "r"(a[2]), "r"(a[3]), "r"(b[0]), "r"(b[1]));
}
__device__ __forceinline__ float warpSum(float v) {
    #pragma unroll
    for (int o = 16; o; o >>= 1) v += __shfl_xor_sync(0xffffffffu, v, o);
    return v;
}
__device__ __forceinline__ float warpMax(float v) {
    #pragma unroll
    for (int o = 16; o; o >>= 1) v = fmaxf(v, __shfl_xor_sync(0xffffffffu, v, o));
    return v;
}

// ---------------------------------------------------------------------------
// tf32 mma.sync GEMM: inputs are PRE-ROUNDED to tf32 grid; no cvt inside.
// C[M,N] = alpha * A[M,K](K-major) x B[N,K](K-major) (+res)
// CTA tile 128x128, K-chunks of 32, 256 threads (8 warps, 4m x 2n).
// ---------------------------------------------------------------------------
struct GArgs {
    const float* A; const float* B; float* C; const float* res;
    long long lda, ldb, ldc;
    int M, N, K;
    float alpha;
    int mode;   // 0 normal, 1 moe gather-A, 2 moe no-gather
    int roundC; // round outputs to tf32 grid (feeds another GEMM)
    long long sAb, sAh, sBb, sBh, sCb, sCh;
    int zmod, groups;
};

__global__ void __launch_bounds__(256) tc_gemm(GArgs g) {
    extern __shared__ float dsmf[];
    const int tid = threadIdx.x, lane = tid & 31, wid = tid >> 5;
    const int wm = wid & 3, wn = wid >> 2;
    const int gq = lane >> 2, qq = lane & 3;

    int m0, Mb;
    const float* Ab = g.A;
    const float* Bb = g.B;
    float* Cb = g.C;
    const float* resb = g.res;
    if (g.mode >= 1) {
        int e = g_tileE[blockIdx.y];
        if (e < 0) return;
        m0 = g_tileR0[blockIdx.y];
        Mb = g_coff[e + 1];
        Bb += (size_t)e * g.N * g.K;
    } else {
        m0 = blockIdx.y * 128;
        Mb = g.M;
        int bz = blockIdx.z;
        int b = bz / g.zmod, h = bz % g.zmod;
        Ab += (size_t)b * g.sAb + (size_t)h * g.sAh;
        Bb += (size_t)b * g.sBb + (size_t)(h / g.groups) * g.sBh;
        Cb += (size_t)b * g.sCb + (size_t)h * g.sCh;
        if (resb) resb += (size_t)b * g.sCb + (size_t)h * g.sCh;
    }
    const int n0 = blockIdx.x * 128;

    __shared__ int rt[128];
    if (tid < 128) {
        int m = m0 + tid;
        int r = (m < Mb) ? m : -1;
        if (g.mode == 1 && r >= 0) r = g_toklist[r];
        rt[tid] = r;
    }
    __syncthreads();

    const uint32_t sbase = smem_to_u32(dsmf);
    const int NC = g.K >> 5;

    auto issue = [&](int c, int s) {
        const int k0 = c << 5;
        #pragma unroll
        for (int p = 0; p < 4; p++) {
            int idx = p * 256 + tid;
            int row = idx >> 3, c4 = idx & 7;
            int r = rt[row];
            const float* src = (r >= 0 ? Ab + (size_t)r * g.lda : Ab) + k0 + c4 * 4;
            uint32_t dst = sbase + (uint32_t)(s * 4608 + row * 36 + c4 * 4) * 4u;
            int sz = (r >= 0) ? 16 : 0;
            asm volatile("cp.async.cg.shared.global [%0], [%1], 16, %2;"
                         :: "r"(dst), "l"(src), "r"(sz) : "memory");
        }
        #pragma unroll
        for (int p = 0; p < 4; p++) {
            int idx = p * 256 + tid;
            int row = idx >> 3, c4 = idx & 7;
            const float* src = Bb + (size_t)(n0 + row) * g.ldb + k0 + c4 * 4;
            uint32_t dst = sbase + (uint32_t)(9216 + s * 4608 + row * 36 + c4 * 4) * 4u;
            asm volatile("cp.async.cg.shared.global [%0], [%1], 16, %2;"
                         :: "r"(dst), "l"(src), "r"(16) : "memory");
        }
    };

    float acc[2][8][4] = {};

    issue(0, 0);
    asm volatile("cp.async.commit_group;" ::: "memory");
    if (NC > 1) issue(1, 1);
    asm volatile("cp.async.commit_group;" ::: "memory");

    const uint32_t* dsum = reinterpret_cast<const uint32_t*>(dsmf);

    for (int c = 0; c < NC; c++) {
        const int s = c & 1;
        asm volatile("cp.async.wait_group 1;" ::: "memory");
        __syncthreads();
        const uint32_t* Asm = dsum + s * 4608;
        const uint32_t* Bsm = dsum + 9216 + s * 4608;
        #pragma unroll
        for (int kk = 0; kk < 4; kk++) {
            const int kb = kk * 8;
            uint32_t af[2][4];
            #pragma unroll
            for (int mt = 0; mt < 2; mt++) {
                int r0 = wm * 32 + mt * 16 + gq;
                af[mt][0] = Asm[r0 * 36 + kb + qq];
                af[mt][1] = Asm[(r0 + 8) * 36 + kb + qq];
                af[mt][2] = Asm[r0 * 36 + kb + qq + 4];
                af[mt][3] = Asm[(r0 + 8) * 36 + kb + qq + 4];
            }
            uint32_t bf[8][2];
            #pragma unroll
            for (int nt = 0; nt < 8; nt++) {
                int c0 = wn * 64 + nt * 8 + gq;
                bf[nt][0] = Bsm[c0 * 36 + kb + qq];
                bf[nt][1] = Bsm[c0 * 36 + kb + qq + 4];
            }
            #pragma unroll
            for (int mt = 0; mt < 2; mt++)
                #pragma unroll
                for (int nt = 0; nt < 8; nt++)
                    mma_tf32(acc[mt][nt], af[mt], bf[nt]);
        }
        __syncthreads();
        if (c + 2 < NC) issue(c + 2, s);
        asm volatile("cp.async.commit_group;" ::: "memory");
    }

    // Epilogue
    #pragma unroll
    for (int mt = 0; mt < 2; mt++) {
        int row = m0 + wm * 32 + mt * 16 + gq;
        #pragma unroll
        for (int half = 0; half < 2; half++) {
            int r = row + half * 8;
            if (r >= Mb) continue;
            float* crow = Cb + (size_t)r * g.ldc + n0 + wn * 64 + 2 * qq;
            const float* rrow = resb ? resb + (size_t)r * g.ldc + n0 + wn * 64 + 2 * qq : nullptr;
            #pragma unroll
            for (int nt = 0; nt < 8; nt++) {
                float2 v;
                v.x = acc[mt][nt][half * 2 + 0] * g.alpha;
                v.y = acc[mt][nt][half * 2 + 1] * g.alpha;
                if (rrow) {
                    float2 rv = *reinterpret_cast<const float2*>(rrow + nt * 8);
                    v.x += rv.x; v.y += rv.y;
                }
                if (g.roundC) { v.x = rntf(v.x); v.y = rntf(v.y); }
                *reinterpret_cast<float2*>(crow + nt * 8) = v;
            }
        }
    }
}

// ---------------------------------------------------------------------------
// Batched tiled transpose (rounds to tf32): in [z][K][N] -> out [z][N][K]
// ---------------------------------------------------------------------------
__global__ void transpose_kernel(const float* __restrict__ in, float* __restrict__ out,
                                 int K, int N) {
    __shared__ float t[32][33];
    size_t zo = (size_t)blockIdx.z * K * N;
    const float* ip = in + zo;
    float* op = out + zo;
    int n0 = blockIdx.x * 32, k0 = blockIdx.y * 32;
    int tx = threadIdx.x & 31, ty = threadIdx.x >> 5;
    #pragma unroll
    for (int i = ty; i < 32; i += 8) t[i][tx] = ip[(size_t)(k0 + i) * N + n0 + tx];
    __syncthreads();
    #pragma unroll
    for (int i = ty; i < 32; i += 8) op[(size_t)(n0 + i) * K + k0 + tx] = rntf(t[tx][i]);
}

// V transpose (rounds): g_v [b*S][512] head kh cols -> g_vT [(b*4+kh)*128 + d][S]
__global__ void vtrans_kernel() {
    __shared__ float t[32][33];
    int z = blockIdx.z, b = z >> 2, kh = z & 3;
    int s0 = blockIdx.x * 32, d0 = blockIdx.y * 32;
    int tx = threadIdx.x & 31, ty = threadIdx.x >> 5;
    #pragma unroll
    for (int i = ty; i < 32; i += 8)
        t[i][tx] = g_v[((size_t)b * nS + s0 + i) * (nNKV * nDH) + kh * nDH + d0 + tx];
    __syncthreads();
    #pragma unroll
    for (int i = ty; i < 32; i += 8)
        g_vT[((size_t)z * nDH + d0 + i) * nS + s0 + tx] = rntf(t[tx][i]);
}

// ---------------------------------------------------------------------------
// RMSNorm. rmsnorm1: rounded out only. rmsnorm2: rounded out + unrounded copy
// (router must see full-precision logit inputs — expert top-2 selection is
// sensitive; this exactly restores the R3-passing semantics).
// ---------------------------------------------------------------------------
template <bool DUAL>
__device__ __forceinline__ void rmsnorm_row(const float* __restrict__ x,
                                            const float* __restrict__ w,
                                            float* __restrict__ out_r,
                                            float* __restrict__ out_f) {
    int row = blockIdx.x;
    const float* xr = x + (size_t)row * nH;
    float ss = 0.f;
    for (int i = threadIdx.x; i < nH; i += blockDim.x) { float v = xr[i]; ss += v * v; }
    __shared__ float sm[8];
    int lane = threadIdx.x & 31, wid = threadIdx.x >> 5;
    ss = warpSum(ss);
    if (lane == 0) sm[wid] = ss;
    __syncthreads();
    if (wid == 0) {
        float v = (lane < 8) ? sm[lane] : 0.f;
        v = warpSum(v);
        if (lane == 0) sm[0] = rsqrtf(v / (float)nH + RMS_EPS);
    }
    __syncthreads();
    float inv = sm[0];
    for (int i = threadIdx.x; i < nH; i += blockDim.x) {
        float v = xr[i] * inv * w[i];
        out_r[(size_t)row * nH + i] = rntf(v);
        if (DUAL) out_f[(size_t)row * nH + i] = v;
    }
}
__global__ void rmsnorm1_kernel(const float* __restrict__ hs, const float* __restrict__ w) {
    rmsnorm_row<false>(hs, w, g_xn, nullptr);
}
__global__ void rmsnorm2_kernel(const float* __restrict__ w) {
    rmsnorm_row<true>(g_hidden, w, g_x2, g_xn);   // g_xn reused: unrounded for router
}

// ---------------------------------------------------------------------------
// RoPE (in-place on q and k; rounds output)
// ---------------------------------------------------------------------------
__global__ void rope_kernel(const float* __restrict__ cosb, const float* __restrict__ sinb) {
    int i = blockIdx.x * blockDim.x + threadIdx.x;
    if (i >= nT * (nNH + nNKV) * 64) return;
    int d  = i & 63;
    int hh = (i >> 6) % (nNH + nNKV);
    int t  = i / (64 * (nNH + nNKV));
    float* ptr = (hh < nNH)
        ? (g_q + (size_t)t * (nNH * nDH) + hh * nDH)
        : (g_k + (size_t)t * (nNKV * nDH) + (hh - nNH) * nDH);
    float x1 = ptr[d], x2 = ptr[d + 64];
    const float* cr = cosb + (size_t)t * nDH;
    const float* sr = sinb + (size_t)t * nDH;
    ptr[d]      = rntf(x1 * cr[d]      - x2 * sr[d]);
    ptr[d + 64] = rntf(x2 * cr[d + 64] + x1 * sr[d + 64]);
}

// ---------------------------------------------------------------------------
// Row softmax over scores — row cached in smem, 1 read + 1 write; rounds out.
// ---------------------------------------------------------------------------
__global__ void __launch_bounds__(256) softmax_kernel() {
    __shared__ float xs[nS];
    __shared__ float sm[8];
    size_t row = blockIdx.x;
    float* p = g_scores + row * (size_t)nS;
    int lane = threadIdx.x & 31, wid = threadIdx.x >> 5;

    float mx = -1e30f;
    for (int i = threadIdx.x; i < nS; i += 256) {
        float v = p[i];
        xs[i] = v;
        mx = fmaxf(mx, v);
    }
    mx = warpMax(mx);
    if (lane == 0) sm[wid] = mx;
    __syncthreads();
    if (wid == 0) {
        float v = (lane < 8) ? sm[lane] : -1e30f;
        v = warpMax(v);
        if (lane == 0) sm[0] = v;
    }
    __syncthreads();
    mx = sm[0];

    float s = 0.f;
    for (int i = threadIdx.x; i < nS; i += 256) {
        float e = expf(xs[i] - mx);
        xs[i] = e;
        s += e;
    }
    s = warpSum(s);
    __syncthreads();
    if (lane == 0) sm[wid] = s;
    __syncthreads();
    if (wid == 0) {
        float v = (lane < 8) ? sm[lane] : 0.f;
        v = warpSum(v);
        if (lane == 0) sm[0] = v;
    }
    __syncthreads();
    float inv = 1.f / sm[0];
    for (int i = threadIdx.x; i < nS; i += 256) p[i] = rntf(xs[i] * inv);
}

// ---------------------------------------------------------------------------
// Router (reads UNROUNDED normed activations from g_xn)
// ---------------------------------------------------------------------------
__global__ void router_kernel(const float* __restrict__ rw) {
    __shared__ float xs[nH];
    __shared__ float lg[nE];
    int t = blockIdx.x;
    for (int i = threadIdx.x; i < nH; i += blockDim.x) xs[i] = g_xn[(size_t)t * nH + i];
    __syncthreads();
    int w = threadIdx.x >> 5, lane = threadIdx.x & 31;
    float s = 0.f;
    for (int i = lane; i < nH; i += 32) s += xs[i] * rw[(size_t)i * nE + w];
    s = warpSum(s);
    if (lane == 0) lg[w] = s;
    __syncthreads();
    if (threadIdx.x == 0) {
        float mx = lg[0];
        #pragma unroll
        for (int e = 1; e < nE; e++) mx = fmaxf(mx, lg[e]);
        float p[nE]; float sum = 0.f;
        #pragma unroll
        for (int e = 0; e < nE; e++) { p[e] = expf(lg[e] - mx); sum += p[e]; }
        #pragma unroll
        for (int e = 0; e < nE; e++) p[e] /= sum;
        int i1 = 0;
        #pragma unroll
        for (int e = 1; e < nE; e++) if (p[e] > p[i1]) i1 = e;
        int i2 = (i1 == 0) ? 1 : 0;
        #pragma unroll
        for (int e = 0; e < nE; e++) if (e != i1 && p[e] > p[i2]) i2 = e;
        float s2 = p[i1] + p[i2];
        g_topi[t * 2] = i1; g_topi[t * 2 + 1] = i2;
        g_topw[t * 2] = p[i1] / s2; g_topw[t * 2 + 1] = p[i2] / s2;
    }
}

// ---------------------------------------------------------------------------
// MoE bookkeeping
// ---------------------------------------------------------------------------
__global__ void reset_kernel() {
    int i = threadIdx.x;
    if (i < nE) { g_counts[i] = 0; g_fill[i] = 0; }
}
__global__ void count_kernel() {
    int t = blockIdx.x * blockDim.x + threadIdx.x;
    if (t >= nT) return;
    atomicAdd(&g_counts[g_topi[t * 2]], 1);
    atomicAdd(&g_counts[g_topi[t * 2 + 1]], 1);
}
__global__ void scan_kernel() {
    if (threadIdx.x != 0) return;
    int off = 0, nt = 0;
    for (int e = 0; e < nE; e++) {
        g_coff[e] = off;
        int ne = g_counts[e];
        int ntl = (ne + 127) >> 7;
        for (int i = 0; i < ntl; i++) { g_tileE[nt] = e; g_tileR0[nt] = off + i * 128; nt++; }
        off += ne;
    }
    g_coff[nE] = off;
    for (int i = nt; i < MAXTILE; i++) g_tileE[i] = -1;
}
__global__ void scatter_kernel() {
    int t = blockIdx.x * blockDim.x + threadIdx.x;
    if (t >= nT) return;
    #pragma unroll
    for (int k = 0; k < 2; k++) {
        int e = g_topi[t * 2 + k];
        int pos = g_coff[e] + atomicAdd(&g_fill[e], 1);
        g_toklist[pos] = t;
        g_slot[t * 2 + k] = pos;
    }
}

__global__ void silu_kernel() {
    size_t i = (size_t)blockIdx.x * blockDim.x + threadIdx.x;
    if (i >= (size_t)GR * nMI) return;
    float gv = g_gbuf[i];
    g_ubuf[i] = rntf(gv * (1.f / (1.f + expf(-gv))) * g_ubuf[i]);
}

__global__ void combine_kernel(float* __restrict__ out) {
    size_t i = (size_t)blockIdx.x * blockDim.x + threadIdx.x;
    if (i >= (size_t)nT * nH) return;
    int t = (int)(i / nH), j = (int)(i % nH);
    float v = g_hidden[i];
    v += g_topw[t * 2]     * g_part[(size_t)g_slot[t * 2]     * nH + j];
    v += g_topw[t * 2 + 1] * g_part[(size_t)g_slot[t * 2 + 1] * nH + j];
    out[i] = v;
}

// ---------------------------------------------------------------------------
// Launch
// ---------------------------------------------------------------------------
static void launch_gemm(const float* A, long long lda, const float* B, long long ldb,
                        float* C, long long ldc, const float* res,
                        int M, int N, int K, float alpha, int mode, int roundC,
                        dim3 grid,
                        long long sAb = 0, long long sAh = 0, long long sBb = 0,
                        long long sBh = 0, long long sCb = 0, long long sCh = 0,
                        int zmod = 1, int groups = 1) {
    GArgs g;
    g.A = A; g.B = B; g.C = C; g.res = res;
    g.lda = lda; g.ldb = ldb; g.ldc = ldc;
    g.M = M; g.N = N; g.K = K; g.alpha = alpha; g.mode = mode; g.roundC = roundC;
    g.sAb = sAb; g.sAh = sAh; g.sBb = sBb; g.sBh = sBh; g.sCb = sCb; g.sCh = sCh;
    g.zmod = zmod; g.groups = groups;
    tc_gemm<<<grid, 256, SMEM_BYTES>>>(g);
}

extern "C" void kernel_launch(void* const* d_in, const int* in_sizes, int n_in,
                              void* d_out, int out_size) {
    const float* hs   = (const float*)d_in[0];
    const float* cosb = (const float*)d_in[1];
    const float* sinb = (const float*)d_in[2];
    const float* wq   = (const float*)d_in[3];
    const float* wk   = (const float*)d_in[4];
    const float* wv   = (const float*)d_in[5];
    const float* wo   = (const float*)d_in[6];
    const float* ln1  = (const float*)d_in[7];
    const float* ln2  = (const float*)d_in[8];
    const float* rw   = (const float*)d_in[9];
    const float* gw   = (const float*)d_in[10];
    const float* uw   = (const float*)d_in[11];
    const float* dw   = (const float*)d_in[12];
    float* out = (float*)d_out;

    static bool attr_set = false;
    if (!attr_set) {
        cudaFuncSetAttribute(tc_gemm, cudaFuncAttributeMaxDynamicSharedMemorySize, SMEM_BYTES);
        attr_set = true;
    }

    float* wqT; cudaGetSymbolAddress((void**)&wqT, g_wqT);
    float* wkT; cudaGetSymbolAddress((void**)&wkT, g_wkT);
    float* wvT; cudaGetSymbolAddress((void**)&wvT, g_wvT);
    float* woT; cudaGetSymbolAddress((void**)&woT, g_woT);
    float* gwT; cudaGetSymbolAddress((void**)&gwT, g_gwT);
    float* uwT; cudaGetSymbolAddress((void**)&uwT, g_uwT);
    float* dwT; cudaGetSymbolAddress((void**)&dwT, g_dwT);
    float* xn;  cudaGetSymbolAddress((void**)&xn, g_xn);
    float* q;   cudaGetSymbolAddress((void**)&q, g_q);
    float* k;   cudaGetSymbolAddress((void**)&k, g_k);
    float* v;   cudaGetSymbolAddress((void**)&v, g_v);
    float* vT;  cudaGetSymbolAddress((void**)&vT, g_vT);
    float* sc;  cudaGetSymbolAddress((void**)&sc, g_scores);
    float* at;  cudaGetSymbolAddress((void**)&at, g_attn);
    float* hid; cudaGetSymbolAddress((void**)&hid, g_hidden);
    float* x2;  cudaGetSymbolAddress((void**)&x2, g_x2);
    float* gb;  cudaGetSymbolAddress((void**)&gb, g_gbuf);
    float* ub;  cudaGetSymbolAddress((void**)&ub, g_ubuf);
    float* pt;  cudaGetSymbolAddress((void**)&pt, g_part);

    reset_kernel<<<1, 32>>>();

    // Weight transposes -> [N][K], tf32-rounded
    transpose_kernel<<<dim3(64, 64, 1), 256>>>(wq, wqT, nH, nNH * nDH);
    transpose_kernel<<<dim3(16, 64, 1), 256>>>(wk, wkT, nH, nNKV * nDH);
    transpose_kernel<<<dim3(16, 64, 1), 256>>>(wv, wvT, nH, nNKV * nDH);
    transpose_kernel<<<dim3(64, 64, 1), 256>>>(wo, woT, nH, nH);
    transpose_kernel<<<dim3(44, 64, nE), 256>>>(gw, gwT, nH, nMI);
    transpose_kernel<<<dim3(44, 64, nE), 256>>>(uw, uwT, nH, nMI);
    transpose_kernel<<<dim3(64, 44, nE), 256>>>(dw, dwT, nMI, nH);

    rmsnorm1_kernel<<<nT, 256>>>(hs, ln1);

    launch_gemm(xn, nH, wqT, nH, q, nNH * nDH, nullptr, nT, nNH * nDH, nH, 1.f, 0, 0,
                dim3(16, 32, 1));
    launch_gemm(xn, nH, wkT, nH, k, nNKV * nDH, nullptr, nT, nNKV * nDH, nH, 1.f, 0, 0,
                dim3(4, 32, 1));
    launch_gemm(xn, nH, wvT, nH, v, nNKV * nDH, nullptr, nT, nNKV * nDH, nH, 1.f, 0, 0,
                dim3(4, 32, 1));

    rope_kernel<<<(nT * (nNH + nNKV) * 64) / 256, 256>>>(cosb, sinb);
    vtrans_kernel<<<dim3(nS / 32, nDH / 32, nB * nNKV), 256>>>();

    // scores = Q K^T * scale
    launch_gemm(q, nNH * nDH, k, nNKV * nDH, sc, nS, nullptr, nS, nS, nDH, QK_SCALE, 0, 0,
                dim3(16, 16, nB * nNH),
                (long long)nS * nNH * nDH, nDH,
                (long long)nS * nNKV * nDH, nDH,
                (long long)nNH * nS * nS, (long long)nS * nS,
                nNH, nNH / nNKV);

    softmax_kernel<<<nB * nNH * nS, 256>>>();

    // attn_out = P @ V (B = V^T), output rounded (feeds WO gemm)
    launch_gemm(sc, nS, vT, nS, at, nH, nullptr, nS, nDH, nS, 1.f, 0, 1,
                dim3(1, 16, nB * nNH),
                (long long)nNH * nS * nS, (long long)nS * nS,
                (long long)nNKV * nDH * nS, (long long)nDH * nS,
                (long long)nS * nH, nDH,
                nNH, nNH / nNKV);

    // hidden = attn @ wo + residual (fp32 out)
    launch_gemm(at, nH, woT, nH, hid, nH, hs, nT, nH, nH, 1.f, 0, 0, dim3(16, 32, 1));

    rmsnorm2_kernel<<<nT, 256>>>(ln2);
    router_kernel<<<nT, 256>>>(rw);

    count_kernel<<<nT / 256, 256>>>();
    scan_kernel<<<1, 1>>>();
    scatter_kernel<<<nT / 256, 256>>>();

    // MoE: gate & up (gathered A), silu (rounds), down
    launch_gemm(x2, nH, gwT, nH, gb, nMI, nullptr, GR, nMI, nH, 1.f, 1, 0, dim3(11, MAXTILE, 1));
    launch_gemm(x2, nH, uwT, nH, ub, nMI, nullptr, GR, nMI, nH, 1.f, 1, 0, dim3(11, MAXTILE, 1));
    silu_kernel<<<((size_t)GR * nMI) / 256, 256>>>();
    launch_gemm(ub, nMI, dwT, nMI, pt, nH, nullptr, GR, nH, nMI, 1.f, 2, 0, dim3(16, MAXTILE, 1));

    combine_kernel<<<((size_t)nT * nH) / 256, 256>>>(out);
}

// round 6
// speedup vs baseline: 3.6322x; 1.1208x over previous
#include <cuda_runtime.h>
#include <cuda_bf16.h>
#include <math.h>
#include <stdint.h>

// ---------------------------------------------------------------------------
// Problem constants
// ---------------------------------------------------------------------------
namespace {
constexpr int nB = 2, nS = 2048, nH = 2048, nNH = 16, nNKV = 4, nDH = 128;
constexpr int nE = 8, nMI = 1408;
constexpr int nT = nB * nS;          // 4096 tokens
constexpr int GR = nT * 2;           // 8192 gathered (token, expert) rows
constexpr int MAXTILE = 72;          // ceil(8192/128) + 8 experts padding
constexpr float RMS_EPS = 1e-6f;
constexpr float QK_SCALE = 0.088388347648318447f;  // 1/sqrt(128)
constexpr int SMEM_FLOATS = 4 * 128 * 36;          // 2 bufs x (A+B) tiles
constexpr int SMEM_BYTES = SMEM_FLOATS * 4;        // 73728

// flash attention smem layout (float indices)
constexpr int FA_QS = 0;                 // Q  [128][132]
constexpr int FA_KS = 16896;             // K  [64][132]
constexpr int FA_VS = 25344;             // V  2 x [64][136]
constexpr int FA_PS = 42752;             // P  [128][68]
constexpr int FA_RM = 51456;             // rowmax exchange [128][2]
constexpr int FA_RL = 51712;             // rowsum exchange [128][2]
constexpr int FA_FLOATS = 51968;
constexpr int FA_BYTES = FA_FLOATS * 4;  // 207872
}

// ---------------------------------------------------------------------------
// Scratch (device globals)
// ---------------------------------------------------------------------------
__device__ float g_xn    [(size_t)nT * nH];   // rmsnorm1 out; later: unrounded rmsnorm2 out
__device__ float g_q     [(size_t)nT * nNH * nDH];
__device__ float g_k     [(size_t)nT * nNKV * nDH];
__device__ float g_v     [(size_t)nT * nNKV * nDH];
__device__ float g_attn  [(size_t)nT * nH];
__device__ float g_hidden[(size_t)nT * nH];
__device__ float g_x2    [(size_t)nT * nH];
__device__ int   g_topi  [nT * 2];
__device__ float g_topw  [nT * 2];
__device__ int   g_counts[nE];
__device__ int   g_fill  [nE];
__device__ int   g_coff  [nE + 1];
__device__ int   g_tileE [MAXTILE];
__device__ int   g_tileR0[MAXTILE];
__device__ int   g_toklist[GR];
__device__ int   g_slot  [nT * 2];
__device__ float g_gbuf  [(size_t)GR * nMI];
__device__ float g_ubuf  [(size_t)GR * nMI];
__device__ float g_part  [(size_t)GR * nH];
// transposed weights [N][K] K-major (tf32-rounded)
__device__ float g_wqT [(size_t)(nNH * nDH) * nH];
__device__ float g_wkT [(size_t)(nNKV * nDH) * nH];
__device__ float g_wvT [(size_t)(nNKV * nDH) * nH];
__device__ float g_woT [(size_t)nH * nH];
__device__ float g_gwT [(size_t)nE * nMI * nH];
__device__ float g_uwT [(size_t)nE * nMI * nH];
__device__ float g_dwT [(size_t)nE * nH * nMI];

// ---------------------------------------------------------------------------
// Helpers
// ---------------------------------------------------------------------------
__device__ __forceinline__ uint32_t smem_to_u32(const void* p) {
    uint32_t a;
    asm("{ .reg .u64 t; cvta.to.shared.u64 t, %1; cvt.u32.u64 %0, t; }" : "=r"(a) : "l"(p));
    return a;
}
__device__ __forceinline__ float rntf(float x) {
    uint32_t r;
    asm("cvt.rna.tf32.f32 %0, %1;" : "=r"(r) : "f"(x));
    return __uint_as_float(r);
}
__device__ __forceinline__ void mma_tf32(float* d, const uint32_t* a, const uint32_t* b) {
    asm volatile("mma.sync.aligned.m16n8k8.row.col.f32.tf32.tf32.f32 "
        "{%0,%1,%2,%3}, {%4,%5,%6,%7}, {%8,%9}, {%0,%1,%2,%3};"
        : "+f"(d[0]), "+f"(d[1]), "+f"(d[2]), "+f"(d[3])
        : "r"(a[0]), "r"(a[1]), "r"(a[2]), "r"(a[3]), "r"(b[0]), "r"(b[1]));
}
__device__ __forceinline__ float warpSum(float v) {
    #pragma unroll
    for (int o = 16; o; o >>= 1) v += __shfl_xor_sync(0xffffffffu, v, o);
    return v;
}

// ---------------------------------------------------------------------------
// tf32 mma.sync GEMM: inputs are PRE-ROUNDED to tf32 grid; no cvt inside.
// C[M,N] = alpha * A[M,K](K-major) x B[N,K](K-major) (+res)
// CTA tile 128x128, K-chunks of 32, 256 threads (8 warps, 4m x 2n).
// ---------------------------------------------------------------------------
struct GArgs {
    const float* A; const float* B; float* C; const float* res;
    long long lda, ldb, ldc;
    int M, N, K;
    float alpha;
    int mode;   // 0 normal, 1 moe gather-A, 2 moe no-gather
    int roundC; // round outputs to tf32 grid (feeds another GEMM)
    long long sAb, sAh, sBb, sBh, sCb, sCh;
    int zmod, groups;
};

__global__ void __launch_bounds__(256) tc_gemm(GArgs g) {
    extern __shared__ float dsmf[];
    const int tid = threadIdx.x, lane = tid & 31, wid = tid >> 5;
    const int wm = wid & 3, wn = wid >> 2;
    const int gq = lane >> 2, qq = lane & 3;

    int m0, Mb;
    const float* Ab = g.A;
    const float* Bb = g.B;
    float* Cb = g.C;
    const float* resb = g.res;
    if (g.mode >= 1) {
        int e = g_tileE[blockIdx.y];
        if (e < 0) return;
        m0 = g_tileR0[blockIdx.y];
        Mb = g_coff[e + 1];
        Bb += (size_t)e * g.N * g.K;
    } else {
        m0 = blockIdx.y * 128;
        Mb = g.M;
        int bz = blockIdx.z;
        int b = bz / g.zmod, h = bz % g.zmod;
        Ab += (size_t)b * g.sAb + (size_t)h * g.sAh;
        Bb += (size_t)b * g.sBb + (size_t)(h / g.groups) * g.sBh;
        Cb += (size_t)b * g.sCb + (size_t)h * g.sCh;
        if (resb) resb += (size_t)b * g.sCb + (size_t)h * g.sCh;
    }
    const int n0 = blockIdx.x * 128;

    __shared__ int rt[128];
    if (tid < 128) {
        int m = m0 + tid;
        int r = (m < Mb) ? m : -1;
        if (g.mode == 1 && r >= 0) r = g_toklist[r];
        rt[tid] = r;
    }
    __syncthreads();

    const uint32_t sbase = smem_to_u32(dsmf);
    const int NC = g.K >> 5;

    auto issue = [&](int c, int s) {
        const int k0 = c << 5;
        #pragma unroll
        for (int p = 0; p < 4; p++) {
            int idx = p * 256 + tid;
            int row = idx >> 3, c4 = idx & 7;
            int r = rt[row];
            const float* src = (r >= 0 ? Ab + (size_t)r * g.lda : Ab) + k0 + c4 * 4;
            uint32_t dst = sbase + (uint32_t)(s * 4608 + row * 36 + c4 * 4) * 4u;
            int sz = (r >= 0) ? 16 : 0;
            asm volatile("cp.async.cg.shared.global [%0], [%1], 16, %2;"
                         :: "r"(dst), "l"(src), "r"(sz) : "memory");
        }
        #pragma unroll
        for (int p = 0; p < 4; p++) {
            int idx = p * 256 + tid;
            int row = idx >> 3, c4 = idx & 7;
            const float* src = Bb + (size_t)(n0 + row) * g.ldb + k0 + c4 * 4;
            uint32_t dst = sbase + (uint32_t)(9216 + s * 4608 + row * 36 + c4 * 4) * 4u;
            asm volatile("cp.async.cg.shared.global [%0], [%1], 16, %2;"
                         :: "r"(dst), "l"(src), "r"(16) : "memory");
        }
    };

    float acc[2][8][4] = {};

    issue(0, 0);
    asm volatile("cp.async.commit_group;" ::: "memory");
    if (NC > 1) issue(1, 1);
    asm volatile("cp.async.commit_group;" ::: "memory");

    const uint32_t* dsum = reinterpret_cast<const uint32_t*>(dsmf);

    for (int c = 0; c < NC; c++) {
        const int s = c & 1;
        asm volatile("cp.async.wait_group 1;" ::: "memory");
        __syncthreads();
        const uint32_t* Asm = dsum + s * 4608;
        const uint32_t* Bsm = dsum + 9216 + s * 4608;
        #pragma unroll
        for (int kk = 0; kk < 4; kk++) {
            const int kb = kk * 8;
            uint32_t af[2][4];
            #pragma unroll
            for (int mt = 0; mt < 2; mt++) {
                int r0 = wm * 32 + mt * 16 + gq;
                af[mt][0] = Asm[r0 * 36 + kb + qq];
                af[mt][1] = Asm[(r0 + 8) * 36 + kb + qq];
                af[mt][2] = Asm[r0 * 36 + kb + qq + 4];
                af[mt][3] = Asm[(r0 + 8) * 36 + kb + qq + 4];
            }
            uint32_t bf[8][2];
            #pragma unroll
            for (int nt = 0; nt < 8; nt++) {
                int c0 = wn * 64 + nt * 8 + gq;
                bf[nt][0] = Bsm[c0 * 36 + kb + qq];
                bf[nt][1] = Bsm[c0 * 36 + kb + qq + 4];
            }
            #pragma unroll
            for (int mt = 0; mt < 2; mt++)
                #pragma unroll
                for (int nt = 0; nt < 8; nt++)
                    mma_tf32(acc[mt][nt], af[mt], bf[nt]);
        }
        __syncthreads();
        if (c + 2 < NC) issue(c + 2, s);
        asm volatile("cp.async.commit_group;" ::: "memory");
    }

    // Epilogue
    #pragma unroll
    for (int mt = 0; mt < 2; mt++) {
        int row = m0 + wm * 32 + mt * 16 + gq;
        #pragma unroll
        for (int half = 0; half < 2; half++) {
            int r = row + half * 8;
            if (r >= Mb) continue;
            float* crow = Cb + (size_t)r * g.ldc + n0 + wn * 64 + 2 * qq;
            const float* rrow = resb ? resb + (size_t)r * g.ldc + n0 + wn * 64 + 2 * qq : nullptr;
            #pragma unroll
            for (int nt = 0; nt < 8; nt++) {
                float2 v;
                v.x = acc[mt][nt][half * 2 + 0] * g.alpha;
                v.y = acc[mt][nt][half * 2 + 1] * g.alpha;
                if (rrow) {
                    float2 rv = *reinterpret_cast<const float2*>(rrow + nt * 8);
                    v.x += rv.x; v.y += rv.y;
                }
                if (g.roundC) { v.x = rntf(v.x); v.y = rntf(v.y); }
                *reinterpret_cast<float2*>(crow + nt * 8) = v;
            }
        }
    }
}

// ---------------------------------------------------------------------------
// Fused flash attention: per CTA one (b,h) and 128 Q rows; stream K/V in
// 64-key tiles; online softmax; O accumulated in registers.
// Q/K pre-rounded by rope, V pre-rounded by its projection epilogue.
// ---------------------------------------------------------------------------
__global__ void __launch_bounds__(256) flash_kernel() {
    extern __shared__ float fs[];
    const int tid = threadIdx.x, lane = tid & 31, wid = tid >> 5;
    const int wm = wid & 3, wn = wid >> 2;
    const int gq = lane >> 2, qq = lane & 3;
    const int bh = blockIdx.y, b = bh >> 4, h = bh & 15, kh = h >> 2;
    const int q0 = blockIdx.x * 128;

    const float* Qg = g_q + ((size_t)(b * nS + q0)) * (nNH * nDH) + h * nDH;
    const float* Kg = g_k + (size_t)b * nS * (nNKV * nDH) + kh * nDH;
    const float* Vg = g_v + (size_t)b * nS * (nNKV * nDH) + kh * nDH;
    float* Og = g_attn + ((size_t)(b * nS + q0)) * nH + h * nDH;

    const uint32_t sb = smem_to_u32(fs);

    // Q tile: 128 rows x 128 floats -> smem stride 132
    #pragma unroll
    for (int p = 0; p < 16; p++) {
        int idx = p * 256 + tid;
        int row = idx >> 5, c4 = idx & 31;
        uint32_t dst = sb + (uint32_t)(FA_QS + row * 132 + c4 * 4) * 4u;
        const float* src = Qg + (size_t)row * (nNH * nDH) + c4 * 4;
        asm volatile("cp.async.cg.shared.global [%0], [%1], 16;"
                     :: "r"(dst), "l"(src) : "memory");
    }
    asm volatile("cp.async.commit_group;" ::: "memory");

    auto issueKV = [&](int it2) {
        const float* kg = Kg + (size_t)(it2 * 64) * (nNKV * nDH);
        const float* vg = Vg + (size_t)(it2 * 64) * (nNKV * nDH);
        const uint32_t vb = (uint32_t)(FA_VS + (it2 & 1) * 8704);
        #pragma unroll
        for (int p = 0; p < 8; p++) {
            int idx = p * 256 + tid;
            int row = idx >> 5, c4 = idx & 31;
            uint32_t dk = sb + (uint32_t)(FA_KS + row * 132 + c4 * 4) * 4u;
            asm volatile("cp.async.cg.shared.global [%0], [%1], 16;"
                         :: "r"(dk), "l"(kg + (size_t)row * (nNKV * nDH) + c4 * 4) : "memory");
            uint32_t dv = sb + (vb + (uint32_t)(row * 136 + c4 * 4)) * 4u;
            asm volatile("cp.async.cg.shared.global [%0], [%1], 16;"
                         :: "r"(dv), "l"(vg + (size_t)row * (nNKV * nDH) + c4 * 4) : "memory");
        }
    };
    issueKV(0);
    asm volatile("cp.async.commit_group;" ::: "memory");

    float accO[2][8][4] = {};
    float rm[2][2] = {{-1e30f, -1e30f}, {-1e30f, -1e30f}};
    float rl[2][2] = {{0.f, 0.f}, {0.f, 0.f}};
    const uint32_t* fsu = reinterpret_cast<const uint32_t*>(fs);

    for (int it = 0; it < nS / 64; it++) {
        asm volatile("cp.async.wait_group 0;" ::: "memory");
        __syncthreads();

        // --- S = Q x K^T (warp tile 32 rows x 32 keys) ---
        float S[2][4][4] = {};
        #pragma unroll
        for (int kc = 0; kc < 16; kc++) {
            const int kb = kc * 8;
            uint32_t af[2][4];
            #pragma unroll
            for (int mt = 0; mt < 2; mt++) {
                int r0 = wm * 32 + mt * 16 + gq;
                af[mt][0] = fsu[FA_QS + r0 * 132 + kb + qq];
                af[mt][1] = fsu[FA_QS + (r0 + 8) * 132 + kb + qq];
                af[mt][2] = fsu[FA_QS + r0 * 132 + kb + qq + 4];
                af[mt][3] = fsu[FA_QS + (r0 + 8) * 132 + kb + qq + 4];
            }
            uint32_t bf[4][2];
            #pragma unroll
            for (int nt = 0; nt < 4; nt++) {
                int c0 = wn * 32 + nt * 8 + gq;
                bf[nt][0] = fsu[FA_KS + c0 * 132 + kb + qq];
                bf[nt][1] = fsu[FA_KS + c0 * 132 + kb + qq + 4];
            }
            #pragma unroll
            for (int mt = 0; mt < 2; mt++)
                #pragma unroll
                for (int nt = 0; nt < 4; nt++)
                    mma_tf32(S[mt][nt], af[mt], bf[nt]);
        }
        __syncthreads();                     // all warps done reading Ksm
        if (it + 1 < nS / 64) issueKV(it + 1);
        asm volatile("cp.async.commit_group;" ::: "memory");

        // --- scale + tile row max ---
        float tmax[2][2] = {{-1e30f, -1e30f}, {-1e30f, -1e30f}};
        #pragma unroll
        for (int mt = 0; mt < 2; mt++)
            #pragma unroll
            for (int nt = 0; nt < 4; nt++)
                #pragma unroll
                for (int c = 0; c < 4; c++) {
                    S[mt][nt][c] *= QK_SCALE;
                    tmax[mt][c >> 1] = fmaxf(tmax[mt][c >> 1], S[mt][nt][c]);
                }
        #pragma unroll
        for (int mt = 0; mt < 2; mt++)
            #pragma unroll
            for (int hf = 0; hf < 2; hf++) {
                float v = tmax[mt][hf];
                v = fmaxf(v, __shfl_xor_sync(0xffffffffu, v, 1));
                v = fmaxf(v, __shfl_xor_sync(0xffffffffu, v, 2));
                tmax[mt][hf] = v;
            }
        if (qq == 0) {
            #pragma unroll
            for (int mt = 0; mt < 2; mt++)
                #pragma unroll
                for (int hf = 0; hf < 2; hf++)
                    fs[FA_RM + (wm * 32 + mt * 16 + hf * 8 + gq) * 2 + wn] = tmax[mt][hf];
        }
        __syncthreads();

        float newm[2][2], sco[2][2];
        #pragma unroll
        for (int mt = 0; mt < 2; mt++)
            #pragma unroll
            for (int hf = 0; hf < 2; hf++) {
                int r = wm * 32 + mt * 16 + hf * 8 + gq;
                float tm = fmaxf(fs[FA_RM + r * 2], fs[FA_RM + r * 2 + 1]);
                float nm = fmaxf(rm[mt][hf], tm);
                sco[mt][hf] = __expf(rm[mt][hf] - nm);
                newm[mt][hf] = nm;
                rm[mt][hf] = nm;
            }

        // --- P = exp(S - newm), write to Psm (tf32-rounded), partial sums ---
        float ps[2][2] = {{0.f, 0.f}, {0.f, 0.f}};
        #pragma unroll
        for (int mt = 0; mt < 2; mt++) {
            int r0 = wm * 32 + mt * 16 + gq;
            #pragma unroll
            for (int nt = 0; nt < 4; nt++) {
                int col = wn * 32 + nt * 8 + 2 * qq;
                float p0 = __expf(S[mt][nt][0] - newm[mt][0]);
                float p1 = __expf(S[mt][nt][1] - newm[mt][0]);
                float p2 = __expf(S[mt][nt][2] - newm[mt][1]);
                float p3 = __expf(S[mt][nt][3] - newm[mt][1]);
                ps[mt][0] += p0 + p1;
                ps[mt][1] += p2 + p3;
                float2 v01 = make_float2(rntf(p0), rntf(p1));
                float2 v23 = make_float2(rntf(p2), rntf(p3));
                *reinterpret_cast<float2*>(&fs[FA_PS + r0 * 68 + col]) = v01;
                *reinterpret_cast<float2*>(&fs[FA_PS + (r0 + 8) * 68 + col]) = v23;
            }
        }
        #pragma unroll
        for (int mt = 0; mt < 2; mt++)
            #pragma unroll
            for (int hf = 0; hf < 2; hf++) {
                float v = ps[mt][hf];
                v += __shfl_xor_sync(0xffffffffu, v, 1);
                v += __shfl_xor_sync(0xffffffffu, v, 2);
                ps[mt][hf] = v;
            }
        if (qq == 0) {
            #pragma unroll
            for (int mt = 0; mt < 2; mt++)
                #pragma unroll
                for (int hf = 0; hf < 2; hf++)
                    fs[FA_RL + (wm * 32 + mt * 16 + hf * 8 + gq) * 2 + wn] = ps[mt][hf];
        }
        __syncthreads();

        #pragma unroll
        for (int mt = 0; mt < 2; mt++)
            #pragma unroll
            for (int hf = 0; hf < 2; hf++) {
                int r = wm * 32 + mt * 16 + hf * 8 + gq;
                float ts = fs[FA_RL + r * 2] + fs[FA_RL + r * 2 + 1];
                rl[mt][hf] = rl[mt][hf] * sco[mt][hf] + ts;
            }
        #pragma unroll
        for (int mt = 0; mt < 2; mt++)
            #pragma unroll
            for (int nt = 0; nt < 8; nt++) {
                accO[mt][nt][0] *= sco[mt][0];
                accO[mt][nt][1] *= sco[mt][0];
                accO[mt][nt][2] *= sco[mt][1];
                accO[mt][nt][3] *= sco[mt][1];
            }

        // --- O += P x V (warp tile 32 rows x 64 dh cols) ---
        const int vbase = FA_VS + (it & 1) * 8704;
        #pragma unroll
        for (int kc = 0; kc < 8; kc++) {
            const int kb = kc * 8;
            uint32_t af[2][4];
            #pragma unroll
            for (int mt = 0; mt < 2; mt++) {
                int r0 = wm * 32 + mt * 16 + gq;
                af[mt][0] = fsu[FA_PS + r0 * 68 + kb + qq];
                af[mt][1] = fsu[FA_PS + (r0 + 8) * 68 + kb + qq];
                af[mt][2] = fsu[FA_PS + r0 * 68 + kb + qq + 4];
                af[mt][3] = fsu[FA_PS + (r0 + 8) * 68 + kb + qq + 4];
            }
            uint32_t bf[8][2];
            #pragma unroll
            for (int nt = 0; nt < 8; nt++) {
                int c0 = wn * 64 + nt * 8 + gq;
                bf[nt][0] = fsu[vbase + (kb + qq) * 136 + c0];
                bf[nt][1] = fsu[vbase + (kb + qq + 4) * 136 + c0];
            }
            #pragma unroll
            for (int mt = 0; mt < 2; mt++)
                #pragma unroll
                for (int nt = 0; nt < 8; nt++)
                    mma_tf32(accO[mt][nt], af[mt], bf[nt]);
        }
    }

    // --- epilogue: O / l, rounded (feeds WO GEMM) ---
    #pragma unroll
    for (int mt = 0; mt < 2; mt++)
        #pragma unroll
        for (int hf = 0; hf < 2; hf++) {
            int r = wm * 32 + mt * 16 + hf * 8 + gq;
            float inv = 1.f / rl[mt][hf];
            #pragma unroll
            for (int nt = 0; nt < 8; nt++) {
                int col = wn * 64 + nt * 8 + 2 * qq;
                float2 v;
                v.x = rntf(accO[mt][nt][hf * 2 + 0] * inv);
                v.y = rntf(accO[mt][nt][hf * 2 + 1] * inv);
                *reinterpret_cast<float2*>(Og + (size_t)r * nH + col) = v;
            }
        }
}

// ---------------------------------------------------------------------------
// Batched tiled transpose (rounds to tf32): in [z][K][N] -> out [z][N][K]
// ---------------------------------------------------------------------------
__global__ void transpose_kernel(const float* __restrict__ in, float* __restrict__ out,
                                 int K, int N) {
    __shared__ float t[32][33];
    size_t zo = (size_t)blockIdx.z * K * N;
    const float* ip = in + zo;
    float* op = out + zo;
    int n0 = blockIdx.x * 32, k0 = blockIdx.y * 32;
    int tx = threadIdx.x & 31, ty = threadIdx.x >> 5;
    #pragma unroll
    for (int i = ty; i < 32; i += 8) t[i][tx] = ip[(size_t)(k0 + i) * N + n0 + tx];
    __syncthreads();
    #pragma unroll
    for (int i = ty; i < 32; i += 8) op[(size_t)(n0 + i) * K + k0 + tx] = rntf(t[tx][i]);
}

// ---------------------------------------------------------------------------
// RMSNorm. rmsnorm1: rounded out only. rmsnorm2: rounded out + unrounded copy
// (router must see full-precision inputs).
// ---------------------------------------------------------------------------
template <bool DUAL>
__device__ __forceinline__ void rmsnorm_row(const float* __restrict__ x,
                                            const float* __restrict__ w,
                                            float* __restrict__ out_r,
                                            float* __restrict__ out_f) {
    int row = blockIdx.x;
    const float* xr = x + (size_t)row * nH;
    float ss = 0.f;
    for (int i = threadIdx.x; i < nH; i += blockDim.x) { float v = xr[i]; ss += v * v; }
    __shared__ float sm[8];
    int lane = threadIdx.x & 31, wid = threadIdx.x >> 5;
    ss = warpSum(ss);
    if (lane == 0) sm[wid] = ss;
    __syncthreads();
    if (wid == 0) {
        float v = (lane < 8) ? sm[lane] : 0.f;
        v = warpSum(v);
        if (lane == 0) sm[0] = rsqrtf(v / (float)nH + RMS_EPS);
    }
    __syncthreads();
    float inv = sm[0];
    for (int i = threadIdx.x; i < nH; i += blockDim.x) {
        float v = xr[i] * inv * w[i];
        out_r[(size_t)row * nH + i] = rntf(v);
        if (DUAL) out_f[(size_t)row * nH + i] = v;
    }
}
__global__ void rmsnorm1_kernel(const float* __restrict__ hs, const float* __restrict__ w) {
    rmsnorm_row<false>(hs, w, g_xn, nullptr);
}
__global__ void rmsnorm2_kernel(const float* __restrict__ w) {
    rmsnorm_row<true>(g_hidden, w, g_x2, g_xn);
}

// ---------------------------------------------------------------------------
// RoPE (in-place on q and k; rounds output)
// ---------------------------------------------------------------------------
__global__ void rope_kernel(const float* __restrict__ cosb, const float* __restrict__ sinb) {
    int i = blockIdx.x * blockDim.x + threadIdx.x;
    if (i >= nT * (nNH + nNKV) * 64) return;
    int d  = i & 63;
    int hh = (i >> 6) % (nNH + nNKV);
    int t  = i / (64 * (nNH + nNKV));
    float* ptr = (hh < nNH)
        ? (g_q + (size_t)t * (nNH * nDH) + hh * nDH)
        : (g_k + (size_t)t * (nNKV * nDH) + (hh - nNH) * nDH);
    float x1 = ptr[d], x2 = ptr[d + 64];
    const float* cr = cosb + (size_t)t * nDH;
    const float* sr = sinb + (size_t)t * nDH;
    ptr[d]      = rntf(x1 * cr[d]      - x2 * sr[d]);
    ptr[d + 64] = rntf(x2 * cr[d + 64] + x1 * sr[d + 64]);
}

// ---------------------------------------------------------------------------
// Router (reads UNROUNDED normed activations from g_xn)
// ---------------------------------------------------------------------------
__global__ void router_kernel(const float* __restrict__ rw) {
    __shared__ float xs[nH];
    __shared__ float lg[nE];
    int t = blockIdx.x;
    for (int i = threadIdx.x; i < nH; i += blockDim.x) xs[i] = g_xn[(size_t)t * nH + i];
    __syncthreads();
    int w = threadIdx.x >> 5, lane = threadIdx.x & 31;
    float s = 0.f;
    for (int i = lane; i < nH; i += 32) s += xs[i] * rw[(size_t)i * nE + w];
    s = warpSum(s);
    if (lane == 0) lg[w] = s;
    __syncthreads();
    if (threadIdx.x == 0) {
        float mx = lg[0];
        #pragma unroll
        for (int e = 1; e < nE; e++) mx = fmaxf(mx, lg[e]);
        float p[nE]; float sum = 0.f;
        #pragma unroll
        for (int e = 0; e < nE; e++) { p[e] = expf(lg[e] - mx); sum += p[e]; }
        #pragma unroll
        for (int e = 0; e < nE; e++) p[e] /= sum;
        int i1 = 0;
        #pragma unroll
        for (int e = 1; e < nE; e++) if (p[e] > p[i1]) i1 = e;
        int i2 = (i1 == 0) ? 1 : 0;
        #pragma unroll
        for (int e = 0; e < nE; e++) if (e != i1 && p[e] > p[i2]) i2 = e;
        float s2 = p[i1] + p[i2];
        g_topi[t * 2] = i1; g_topi[t * 2 + 1] = i2;
        g_topw[t * 2] = p[i1] / s2; g_topw[t * 2 + 1] = p[i2] / s2;
    }
}

// ---------------------------------------------------------------------------
// MoE bookkeeping
// ---------------------------------------------------------------------------
__global__ void reset_kernel() {
    int i = threadIdx.x;
    if (i < nE) { g_counts[i] = 0; g_fill[i] = 0; }
}
__global__ void count_kernel() {
    int t = blockIdx.x * blockDim.x + threadIdx.x;
    if (t >= nT) return;
    atomicAdd(&g_counts[g_topi[t * 2]], 1);
    atomicAdd(&g_counts[g_topi[t * 2 + 1]], 1);
}
__global__ void scan_kernel() {
    if (threadIdx.x != 0) return;
    int off = 0, nt = 0;
    for (int e = 0; e < nE; e++) {
        g_coff[e] = off;
        int ne = g_counts[e];
        int ntl = (ne + 127) >> 7;
        for (int i = 0; i < ntl; i++) { g_tileE[nt] = e; g_tileR0[nt] = off + i * 128; nt++; }
        off += ne;
    }
    g_coff[nE] = off;
    for (int i = nt; i < MAXTILE; i++) g_tileE[i] = -1;
}
__global__ void scatter_kernel() {
    int t = blockIdx.x * blockDim.x + threadIdx.x;
    if (t >= nT) return;
    #pragma unroll
    for (int k = 0; k < 2; k++) {
        int e = g_topi[t * 2 + k];
        int pos = g_coff[e] + atomicAdd(&g_fill[e], 1);
        g_toklist[pos] = t;
        g_slot[t * 2 + k] = pos;
    }
}

__global__ void silu_kernel() {
    size_t i = (size_t)blockIdx.x * blockDim.x + threadIdx.x;
    if (i >= (size_t)GR * nMI) return;
    float gv = g_gbuf[i];
    g_ubuf[i] = rntf(gv * (1.f / (1.f + expf(-gv))) * g_ubuf[i]);
}

__global__ void combine_kernel(float* __restrict__ out) {
    size_t i = (size_t)blockIdx.x * blockDim.x + threadIdx.x;
    if (i >= (size_t)nT * nH) return;
    int t = (int)(i / nH), j = (int)(i % nH);
    float v = g_hidden[i];
    v += g_topw[t * 2]     * g_part[(size_t)g_slot[t * 2]     * nH + j];
    v += g_topw[t * 2 + 1] * g_part[(size_t)g_slot[t * 2 + 1] * nH + j];
    out[i] = v;
}

// ---------------------------------------------------------------------------
// Launch
// ---------------------------------------------------------------------------
static void launch_gemm(const float* A, long long lda, const float* B, long long ldb,
                        float* C, long long ldc, const float* res,
                        int M, int N, int K, float alpha, int mode, int roundC,
                        dim3 grid,
                        long long sAb = 0, long long sAh = 0, long long sBb = 0,
                        long long sBh = 0, long long sCb = 0, long long sCh = 0,
                        int zmod = 1, int groups = 1) {
    GArgs g;
    g.A = A; g.B = B; g.C = C; g.res = res;
    g.lda = lda; g.ldb = ldb; g.ldc = ldc;
    g.M = M; g.N = N; g.K = K; g.alpha = alpha; g.mode = mode; g.roundC = roundC;
    g.sAb = sAb; g.sAh = sAh; g.sBb = sBb; g.sBh = sBh; g.sCb = sCb; g.sCh = sCh;
    g.zmod = zmod; g.groups = groups;
    tc_gemm<<<grid, 256, SMEM_BYTES>>>(g);
}

extern "C" void kernel_launch(void* const* d_in, const int* in_sizes, int n_in,
                              void* d_out, int out_size) {
    const float* hs   = (const float*)d_in[0];
    const float* cosb = (const float*)d_in[1];
    const float* sinb = (const float*)d_in[2];
    const float* wq   = (const float*)d_in[3];
    const float* wk   = (const float*)d_in[4];
    const float* wv   = (const float*)d_in[5];
    const float* wo   = (const float*)d_in[6];
    const float* ln1  = (const float*)d_in[7];
    const float* ln2  = (const float*)d_in[8];
    const float* rw   = (const float*)d_in[9];
    const float* gw   = (const float*)d_in[10];
    const float* uw   = (const float*)d_in[11];
    const float* dw   = (const float*)d_in[12];
    float* out = (float*)d_out;

    static bool attr_set = false;
    if (!attr_set) {
        cudaFuncSetAttribute(tc_gemm, cudaFuncAttributeMaxDynamicSharedMemorySize, SMEM_BYTES);
        cudaFuncSetAttribute(flash_kernel, cudaFuncAttributeMaxDynamicSharedMemorySize, FA_BYTES);
        attr_set = true;
    }

    float* wqT; cudaGetSymbolAddress((void**)&wqT, g_wqT);
    float* wkT; cudaGetSymbolAddress((void**)&wkT, g_wkT);
    float* wvT; cudaGetSymbolAddress((void**)&wvT, g_wvT);
    float* woT; cudaGetSymbolAddress((void**)&woT, g_woT);
    float* gwT; cudaGetSymbolAddress((void**)&gwT, g_gwT);
    float* uwT; cudaGetSymbolAddress((void**)&uwT, g_uwT);
    float* dwT; cudaGetSymbolAddress((void**)&dwT, g_dwT);
    float* xn;  cudaGetSymbolAddress((void**)&xn, g_xn);
    float* q;   cudaGetSymbolAddress((void**)&q, g_q);
    float* k;   cudaGetSymbolAddress((void**)&k, g_k);
    float* v;   cudaGetSymbolAddress((void**)&v, g_v);
    float* at;  cudaGetSymbolAddress((void**)&at, g_attn);
    float* hid; cudaGetSymbolAddress((void**)&hid, g_hidden);
    float* x2;  cudaGetSymbolAddress((void**)&x2, g_x2);
    float* gb;  cudaGetSymbolAddress((void**)&gb, g_gbuf);
    float* ub;  cudaGetSymbolAddress((void**)&ub, g_ubuf);
    float* pt;  cudaGetSymbolAddress((void**)&pt, g_part);

    reset_kernel<<<1, 32>>>();

    // Weight transposes -> [N][K], tf32-rounded
    transpose_kernel<<<dim3(64, 64, 1), 256>>>(wq, wqT, nH, nNH * nDH);
    transpose_kernel<<<dim3(16, 64, 1), 256>>>(wk, wkT, nH, nNKV * nDH);
    transpose_kernel<<<dim3(16, 64, 1), 256>>>(wv, wvT, nH, nNKV * nDH);
    transpose_kernel<<<dim3(64, 64, 1), 256>>>(wo, woT, nH, nH);
    transpose_kernel<<<dim3(44, 64, nE), 256>>>(gw, gwT, nH, nMI);
    transpose_kernel<<<dim3(44, 64, nE), 256>>>(uw, uwT, nH, nMI);
    transpose_kernel<<<dim3(64, 44, nE), 256>>>(dw, dwT, nMI, nH);

    rmsnorm1_kernel<<<nT, 256>>>(hs, ln1);

    launch_gemm(xn, nH, wqT, nH, q, nNH * nDH, nullptr, nT, nNH * nDH, nH, 1.f, 0, 0,
                dim3(16, 32, 1));
    launch_gemm(xn, nH, wkT, nH, k, nNKV * nDH, nullptr, nT, nNKV * nDH, nH, 1.f, 0, 0,
                dim3(4, 32, 1));
    launch_gemm(xn, nH, wvT, nH, v, nNKV * nDH, nullptr, nT, nNKV * nDH, nH, 1.f, 0, 1,
                dim3(4, 32, 1));   // V rounded: feeds flash AV

    rope_kernel<<<(nT * (nNH + nNKV) * 64) / 256, 256>>>(cosb, sinb);

    // fused attention: QK + online softmax + AV
    flash_kernel<<<dim3(nS / 128, nB * nNH), 256, FA_BYTES>>>();

    // hidden = attn @ wo + residual (fp32 out)
    launch_gemm(at, nH, woT, nH, hid, nH, hs, nT, nH, nH, 1.f, 0, 0, dim3(16, 32, 1));

    rmsnorm2_kernel<<<nT, 256>>>(ln2);
    router_kernel<<<nT, 256>>>(rw);

    count_kernel<<<nT / 256, 256>>>();
    scan_kernel<<<1, 1>>>();
    scatter_kernel<<<nT / 256, 256>>>();

    // MoE: gate & up (gathered A), silu (rounds), down
    launch_gemm(x2, nH, gwT, nH, gb, nMI, nullptr, GR, nMI, nH, 1.f, 1, 0, dim3(11, MAXTILE, 1));
    launch_gemm(x2, nH, uwT, nH, ub, nMI, nullptr, GR, nMI, nH, 1.f, 1, 0, dim3(11, MAXTILE, 1));
    silu_kernel<<<((size_t)GR * nMI) / 256, 256>>>();
    launch_gemm(ub, nMI, dwT, nMI, pt, nH, nullptr, GR, nH, nMI, 1.f, 2, 0, dim3(16, MAXTILE, 1));

    combine_kernel<<<((size_t)nT * nH) / 256, 256>>>(out);
}